// round 6
// baseline (speedup 1.0000x reference)
#include <cuda_runtime.h>
#include <stdint.h>
#include <math.h>

#define Bq 512
#define Tq 512
#define Fq 52
#define Eq 64
#define Hq 128
#define G4q 512
#define NROWS (Bq*Tq)

// Scratch (device globals; no dynamic allocation allowed)
__device__ float g_henc[NROWS * Eq];          // 64 MB  [row][64]
__device__ float g_gx[NROWS * G4q];           // 512 MB [t][b][512]
__device__ float g_hfin[Bq * Hq];             // final hidden state

// ---------------------------------------------------------------------------
// helpers
// ---------------------------------------------------------------------------
__device__ __forceinline__ unsigned smem_u32(const void* p) {
    unsigned a;
    asm("{ .reg .u64 t; cvta.to.shared.u64 t, %1; cvt.u32.u64 %0, t; }"
        : "=r"(a) : "l"(p));
    return a;
}

__device__ __forceinline__ float sigf(float x) {
    return __fdividef(1.f, 1.f + __expf(-x));
}
__device__ __forceinline__ float tanhf_s(float x) {
    float ax = fabsf(x);
    float e  = __expf(-2.f * ax);            // in (0,1], never overflows
    float r  = __fdividef(1.f - e, 1.f + e);
    return copysignf(r, x);
}

// packed f32x2 fma: d = a*b + d  (two independent fp32 FMAs, one FFMA2)
__device__ __forceinline__ void ffma2(unsigned long long& d,
                                      unsigned long long a,
                                      unsigned long long b) {
    asm("fma.rn.f32x2 %0, %1, %2, %0;" : "+l"(d) : "l"(a), "l"(b));
}
__device__ __forceinline__ float f32x2_hsum(unsigned long long v) {
    unsigned lo = (unsigned)v, hi = (unsigned)(v >> 32);
    return __uint_as_float(lo) + __uint_as_float(hi);
}

// ---------------------------------------------------------------------------
// Fused encoder: h_enc = relu(relu(x @ W1^T + b1) @ W2^T + b2)
// ---------------------------------------------------------------------------
#define ENC_SMEM_FLOATS (64*53 + 52*128 + 64*128 + 128*64 + 128 + 64)

__global__ __launch_bounds__(256) void enc_kernel(
    const float* __restrict__ x,
    const float* __restrict__ W1, const float* __restrict__ b1,
    const float* __restrict__ W2, const float* __restrict__ b2)
{
    extern __shared__ float sm[];
    float* xs  = sm;                 // [64][53]
    float* w1t = xs  + 64*53;        // [52][128]
    float* h1s = w1t + 52*128;       // [64][128]
    float* w2t = h1s + 64*128;       // [128][64]
    float* b1s = w2t + 128*64;
    float* b2s = b1s + 128;

    const int tid = threadIdx.x;
    const int row0 = blockIdx.x * 64;

    for (int idx = tid; idx < 128*52; idx += 256) {
        int c = idx / 52, k = idx % 52;
        w1t[k*128 + c] = W1[idx];
    }
    for (int idx = tid; idx < 64*128; idx += 256) {
        int e = idx / 128, k = idx % 128;
        w2t[k*64 + e] = W2[idx];
    }
    if (tid < 128) b1s[tid] = b1[tid];
    if (tid < 64)  b2s[tid] = b2[tid];
    for (int idx = tid; idx < 64*52; idx += 256) {
        int r = idx / 52, k = idx % 52;
        xs[r*53 + k] = x[(size_t)(row0 + r) * Fq + k];
    }
    __syncthreads();

    // layer 1
    {
        const int cg = tid & 15, rg = tid >> 4;
        const int c0 = cg * 8, r0 = rg * 4;
        float acc[4][8];
        #pragma unroll
        for (int i = 0; i < 4; i++)
            #pragma unroll
            for (int j = 0; j < 8; j++) acc[i][j] = 0.f;

        #pragma unroll 4
        for (int k = 0; k < Fq; k++) {
            float4 wa = *(const float4*)(w1t + k*128 + c0);
            float4 wb = *(const float4*)(w1t + k*128 + c0 + 4);
            #pragma unroll
            for (int i = 0; i < 4; i++) {
                float xv = xs[(r0 + i)*53 + k];
                acc[i][0] += xv * wa.x; acc[i][1] += xv * wa.y;
                acc[i][2] += xv * wa.z; acc[i][3] += xv * wa.w;
                acc[i][4] += xv * wb.x; acc[i][5] += xv * wb.y;
                acc[i][6] += xv * wb.z; acc[i][7] += xv * wb.w;
            }
        }
        #pragma unroll
        for (int i = 0; i < 4; i++)
            #pragma unroll
            for (int j = 0; j < 8; j++) {
                float v = acc[i][j] + b1s[c0 + j];
                h1s[(r0 + i)*128 + c0 + j] = v > 0.f ? v : 0.f;
            }
    }
    __syncthreads();

    // layer 2
    {
        const int cg = tid & 15, rg = tid >> 4;
        const int c0 = cg * 4, r0 = rg * 4;
        float acc[4][4];
        #pragma unroll
        for (int i = 0; i < 4; i++)
            #pragma unroll
            for (int j = 0; j < 4; j++) acc[i][j] = 0.f;

        #pragma unroll 4
        for (int k = 0; k < Hq; k++) {
            float4 w = *(const float4*)(w2t + k*64 + c0);
            #pragma unroll
            for (int i = 0; i < 4; i++) {
                float xv = h1s[(r0 + i)*128 + k];
                acc[i][0] += xv * w.x; acc[i][1] += xv * w.y;
                acc[i][2] += xv * w.z; acc[i][3] += xv * w.w;
            }
        }
        #pragma unroll
        for (int i = 0; i < 4; i++) {
            float4 o;
            float v0 = acc[i][0] + b2s[c0+0]; o.x = v0 > 0.f ? v0 : 0.f;
            float v1 = acc[i][1] + b2s[c0+1]; o.y = v1 > 0.f ? v1 : 0.f;
            float v2 = acc[i][2] + b2s[c0+2]; o.z = v2 > 0.f ? v2 : 0.f;
            float v3 = acc[i][3] + b2s[c0+3]; o.w = v3 > 0.f ? v3 : 0.f;
            *(float4*)(g_henc + (size_t)(row0 + r0 + i) * Eq + c0) = o;
        }
    }
}

// ---------------------------------------------------------------------------
// gx = h_enc @ W_ih^T + (b_ih + b_hh), written as gx[t][b][512]
// ---------------------------------------------------------------------------
#define GX_SMEM_FLOATS (64*64 + 64*128)

__global__ __launch_bounds__(256) void gx_kernel(
    const float* __restrict__ Wih,
    const float* __restrict__ bih, const float* __restrict__ bhh)
{
    extern __shared__ float sm[];
    float* hes = sm;            // [64][64]
    float* wt  = hes + 64*64;   // [64][128]

    const int tid = threadIdx.x;
    const int row0 = blockIdx.x * 64;
    const int cbase = blockIdx.y * 128;

    for (int idx = tid; idx < 64*64/4; idx += 256)
        ((float4*)hes)[idx] = ((const float4*)(g_henc + (size_t)row0 * Eq))[idx];
    for (int idx = tid; idx < 128*64; idx += 256) {
        int c = idx / 64, k = idx % 64;
        wt[k*128 + c] = Wih[(size_t)(cbase + c) * Eq + k];
    }
    __syncthreads();

    const int cg = tid & 15, rg = tid >> 4;
    const int c0 = cg * 8, r0 = rg * 4;
    float acc[4][8];
    #pragma unroll
    for (int i = 0; i < 4; i++)
        #pragma unroll
        for (int j = 0; j < 8; j++) acc[i][j] = 0.f;

    #pragma unroll 4
    for (int k = 0; k < Eq; k++) {
        float4 wa = *(const float4*)(wt + k*128 + c0);
        float4 wb = *(const float4*)(wt + k*128 + c0 + 4);
        #pragma unroll
        for (int i = 0; i < 4; i++) {
            float xv = hes[(r0 + i)*64 + k];
            acc[i][0] += xv * wa.x; acc[i][1] += xv * wa.y;
            acc[i][2] += xv * wa.z; acc[i][3] += xv * wa.w;
            acc[i][4] += xv * wb.x; acc[i][5] += xv * wb.y;
            acc[i][6] += xv * wb.z; acc[i][7] += xv * wb.w;
        }
    }

    #pragma unroll
    for (int i = 0; i < 4; i++) {
        int row = row0 + r0 + i;
        int b = row / Tq, t = row % Tq;
        size_t base = ((size_t)t * Bq + b) * G4q + cbase + c0;
        float4 oa, ob;
        oa.x = acc[i][0] + bih[cbase+c0+0] + bhh[cbase+c0+0];
        oa.y = acc[i][1] + bih[cbase+c0+1] + bhh[cbase+c0+1];
        oa.z = acc[i][2] + bih[cbase+c0+2] + bhh[cbase+c0+2];
        oa.w = acc[i][3] + bih[cbase+c0+3] + bhh[cbase+c0+3];
        ob.x = acc[i][4] + bih[cbase+c0+4] + bhh[cbase+c0+4];
        ob.y = acc[i][5] + bih[cbase+c0+5] + bhh[cbase+c0+5];
        ob.z = acc[i][6] + bih[cbase+c0+6] + bhh[cbase+c0+6];
        ob.w = acc[i][7] + bih[cbase+c0+7] + bhh[cbase+c0+7];
        *(float4*)(g_gx + base)     = oa;
        *(float4*)(g_gx + base + 4) = ob;
    }
}

// ---------------------------------------------------------------------------
// Persistent LSTM, 512 threads (16 warps = 4/SMSP for latency hiding).
// 64 clusters x 2 CTAs. Cluster cl owns batches [cl*8, cl*8+8).
// CTA rank r owns gate columns [r*64, r*64+64) for all 4 gates (256 cols).
// Weights smem-resident: ws[col][132] (pad 132 -> conflict-free LDS.128,
//   lane stride 528 B => banks 4*d mod 32, distinct within 8-lane phase).
// GEMM mapping: col = tid&255 (g=col>>6, jl=col&63), bhalf = tid>>8;
//   thread tile = 1 col x 4 batches: 32 w-LDS.128 + 128 h-LDS.128 (broadcast)
//   + 256 FFMA2 per step.
// Epilogue mapping: 1 (batch,j) per thread: jj = tid&63, bl = tid>>6.
// ---------------------------------------------------------------------------
#define L_WS_STRIDE 132
#define L_WS_FLOATS (256*L_WS_STRIDE)    // 33792 floats (135 KB)
#define L_HS_FLOATS (2*8*128)            // ping-pong h buffers
#define L_GS_FLOATS (256*9)              // gate transpose buffer [256][9]
#define L_SMEM_FLOATS (L_WS_FLOATS + L_HS_FLOATS + L_GS_FLOATS)

__global__ __launch_bounds__(512, 1) __cluster_dims__(2, 1, 1)
void lstm_persist_kernel(const float* __restrict__ Whh)
{
    extern __shared__ float sm[];
    float* ws  = sm;                            // [256][132]
    float* hs  = sm + L_WS_FLOATS;              // [2][8][128]
    float* gsm = sm + L_WS_FLOATS + L_HS_FLOATS;// [256][9]

    const int tid = threadIdx.x;
    unsigned rank;
    asm("mov.u32 %0, %%cluster_ctarank;" : "=r"(rank));
    const int cl = blockIdx.x >> 1;          // cluster id 0..63
    const int j0 = (int)rank * 64;           // my j-half base

    // Stage weights once: ws[col][k] = Whh[(g*128 + j0 + jl)*128 + k],
    // col = g*64 + jl
    for (int idx = tid; idx < 256*128; idx += 512) {
        int col = idx >> 7;
        int k   = idx & 127;
        int g   = col >> 6;
        int jl  = col & 63;
        ws[col * L_WS_STRIDE + k] = Whh[((g << 7) + j0 + jl) * Hq + k];
    }
    // zero h buffers
    for (int idx = tid; idx < L_HS_FLOATS; idx += 512) hs[idx] = 0.f;
    __syncthreads();
    asm volatile("barrier.cluster.arrive.aligned;" ::: "memory");
    asm volatile("barrier.cluster.wait.aligned;" ::: "memory");

    // GEMM mapping
    const int col = tid & 255;
    const int bh  = tid >> 8;        // 0 or 1
    const int bl0 = bh * 4;
    // epilogue mapping
    const int jj  = tid & 63;
    const int bl  = tid >> 6;        // 0..7
    const int jglob = j0 + jj;

    // peer smem base for hs
    unsigned hs_loc = smem_u32(hs);
    unsigned hs_peer;
    asm("mapa.shared::cluster.u32 %0, %1, %2;"
        : "=r"(hs_peer) : "r"(hs_loc), "r"(rank ^ 1u));

    const double2* wp = (const double2*)(ws + col * L_WS_STRIDE);

    float creg = 0.f;
    int p = 0;

    const size_t gx_stride_t = (size_t)Bq * G4q;
    const float* gx_b = g_gx + (size_t)(cl * 8 + bl) * G4q + jglob;

    for (int t = 0; t < Tq; t++) {
        // prefetch gx for this step (epilogue mapping; consumed after GEMM)
        const float* gxp = gx_b + (size_t)t * gx_stride_t;
        float gxr[4];
        #pragma unroll
        for (int g = 0; g < 4; g++) gxr[g] = __ldg(gxp + g * Hq);

        // ---- GEMM: acc2[b] = sum_k h[bl0+b][k] * w_col[k] (f32x2) ----
        unsigned long long acc2[4];
        #pragma unroll
        for (int b = 0; b < 4; b++) acc2[b] = 0ull;

        const double2* hp = (const double2*)(hs + p * 1024 + bl0 * 128);
        // hp[b*32 + k4]: h[bl0+b][4k4 .. 4k4+3]

        #pragma unroll
        for (int k4 = 0; k4 < 32; k4++) {
            double2 w = wp[k4];
            unsigned long long w01 = (unsigned long long)__double_as_longlong(w.x);
            unsigned long long w23 = (unsigned long long)__double_as_longlong(w.y);
            #pragma unroll
            for (int b = 0; b < 4; b++) {
                double2 h = hp[b * 32 + k4];  // broadcast across warp lanes
                ffma2(acc2[b], (unsigned long long)__double_as_longlong(h.x), w01);
                ffma2(acc2[b], (unsigned long long)__double_as_longlong(h.y), w23);
            }
        }

        // ---- gate transpose via smem ----
        {
            float* gp = gsm + col * 9 + bl0;
            #pragma unroll
            for (int b = 0; b < 4; b++) gp[b] = f32x2_hsum(acc2[b]);
        }
        __syncthreads();

        // ---- epilogue: 1 (batch, j) per thread ----
        const int pw = p ^ 1;
        {
            float vi = gsm[(0*64 + jj)*9 + bl] + gxr[0];
            float vf = gsm[(1*64 + jj)*9 + bl] + gxr[1];
            float vg = gsm[(2*64 + jj)*9 + bl] + gxr[2];
            float vo = gsm[(3*64 + jj)*9 + bl] + gxr[3];
            float si = sigf(vi);
            float sf = sigf(vf);
            float so = sigf(vo);
            float tg = tanhf_s(vg);
            float cn = sf * creg + si * tg;
            creg = cn;
            float hn = so * tanhf_s(cn);
            int off = pw * 1024 + bl * 128 + jglob;
            hs[off] = hn;
            asm volatile("st.shared::cluster.f32 [%0], %1;"
                         :: "r"(hs_peer + (unsigned)off * 4u), "f"(hn)
                         : "memory");
        }

        // step barrier: orders h writes (incl. DSMEM) before peer's reads,
        // also separates gsm reuse across steps
        asm volatile("barrier.cluster.arrive.aligned;" ::: "memory");
        asm volatile("barrier.cluster.wait.aligned;" ::: "memory");
        p ^= 1;
    }

    // final h is in hs[0] (512 steps, even). rank 0 publishes to global.
    if (rank == 0) {
        float* dst = g_hfin + (size_t)(cl * 8) * Hq;
        for (int idx = tid; idx < 8 * 128; idx += 512)
            dst[idx] = hs[idx];
    }
}

// ---------------------------------------------------------------------------
// Classifier: out = h_final @ Wc^T + bc, [512 x 21], K=128
// ---------------------------------------------------------------------------
__global__ void cls_kernel(const float* __restrict__ Wc,
                           const float* __restrict__ bc,
                           float* __restrict__ out)
{
    int gid = blockIdx.x * blockDim.x + threadIdx.x;
    if (gid >= Bq * 21) return;
    int b = gid / 21, c = gid % 21;
    const float* h = g_hfin + b * Hq;
    const float* w = Wc + c * Hq;
    float s = 0.f;
    #pragma unroll 8
    for (int k = 0; k < Hq; k++) s += h[k] * w[k];
    out[gid] = s + bc[c];
}

// ---------------------------------------------------------------------------
extern "C" void kernel_launch(void* const* d_in, const int* in_sizes, int n_in,
                              void* d_out, int out_size)
{
    (void)in_sizes; (void)n_in; (void)out_size;
    const float* x   = (const float*)d_in[0];
    const float* W1  = (const float*)d_in[1];
    const float* b1  = (const float*)d_in[2];
    const float* W2  = (const float*)d_in[3];
    const float* b2  = (const float*)d_in[4];
    const float* Wih = (const float*)d_in[5];
    const float* Whh = (const float*)d_in[6];
    const float* bih = (const float*)d_in[7];
    const float* bhh = (const float*)d_in[8];
    const float* Wc  = (const float*)d_in[9];
    const float* bc  = (const float*)d_in[10];
    float* out = (float*)d_out;

    cudaFuncSetAttribute(enc_kernel, cudaFuncAttributeMaxDynamicSharedMemorySize,
                         ENC_SMEM_FLOATS * (int)sizeof(float));
    cudaFuncSetAttribute(gx_kernel, cudaFuncAttributeMaxDynamicSharedMemorySize,
                         GX_SMEM_FLOATS * (int)sizeof(float));
    cudaFuncSetAttribute(lstm_persist_kernel, cudaFuncAttributeMaxDynamicSharedMemorySize,
                         L_SMEM_FLOATS * (int)sizeof(float));

    enc_kernel<<<NROWS/64, 256, ENC_SMEM_FLOATS * sizeof(float)>>>(x, W1, b1, W2, b2);

    gx_kernel<<<dim3(NROWS/64, 4), 256, GX_SMEM_FLOATS * sizeof(float)>>>(Wih, bih, bhh);

    lstm_persist_kernel<<<128, 512, L_SMEM_FLOATS * sizeof(float)>>>(Whh);

    cls_kernel<<<(Bq*21 + 255)/256, 256>>>(Wc, bc, out);
}

// round 8
// speedup vs baseline: 1.4815x; 1.4815x over previous
#include <cuda_runtime.h>
#include <cuda_bf16.h>
#include <stdint.h>
#include <math.h>

#define Bq 512
#define Tq 512
#define Fq 52
#define Eq 64
#define Hq 128
#define G4q 512
#define NROWS (Bq*Tq)

// Scratch (device globals; no dynamic allocation allowed)
__device__ float g_henc[NROWS * Eq];          // 64 MB  [row][64]
__device__ float g_gx[NROWS * G4q];           // 512 MB [t][b][512]
__device__ float g_hfin[Bq * Hq];             // final hidden state

// ---------------------------------------------------------------------------
// helpers
// ---------------------------------------------------------------------------
__device__ __forceinline__ unsigned smem_u32(const void* p) {
    unsigned a;
    asm("{ .reg .u64 t; cvta.to.shared.u64 t, %1; cvt.u32.u64 %0, t; }"
        : "=r"(a) : "l"(p));
    return a;
}

__device__ __forceinline__ float sigf(float x) {
    return __fdividef(1.f, 1.f + __expf(-x));
}
__device__ __forceinline__ float tanhf_s(float x) {
    float ax = fabsf(x);
    float e  = __expf(-2.f * ax);            // in (0,1], never overflows
    float r  = __fdividef(1.f - e, 1.f + e);
    return copysignf(r, x);
}

// pack two bf16 (e0 -> low half, e1 -> high half)
__device__ __forceinline__ unsigned pack_bf16(__nv_bfloat16 e0, __nv_bfloat16 e1) {
    return ((unsigned)__bfloat16_as_ushort(e1) << 16) |
           (unsigned)__bfloat16_as_ushort(e0);
}

// m16n8k16 row.col f32.bf16.bf16.f32 (baseline PTX, sm_80+)
__device__ __forceinline__ void mma_bf16(float c[4], const unsigned a[4],
                                         unsigned b0, unsigned b1) {
    asm volatile(
        "mma.sync.aligned.m16n8k16.row.col.f32.bf16.bf16.f32 "
        "{%0,%1,%2,%3}, {%4,%5,%6,%7}, {%8,%9}, {%0,%1,%2,%3};"
        : "+f"(c[0]), "+f"(c[1]), "+f"(c[2]), "+f"(c[3])
        : "r"(a[0]), "r"(a[1]), "r"(a[2]), "r"(a[3]), "r"(b0), "r"(b1));
}

// ---------------------------------------------------------------------------
// Fused encoder: h_enc = relu(relu(x @ W1^T + b1) @ W2^T + b2)
// ---------------------------------------------------------------------------
#define ENC_SMEM_FLOATS (64*53 + 52*128 + 64*128 + 128*64 + 128 + 64)

__global__ __launch_bounds__(256) void enc_kernel(
    const float* __restrict__ x,
    const float* __restrict__ W1, const float* __restrict__ b1,
    const float* __restrict__ W2, const float* __restrict__ b2)
{
    extern __shared__ float sm[];
    float* xs  = sm;                 // [64][53]
    float* w1t = xs  + 64*53;        // [52][128]
    float* h1s = w1t + 52*128;       // [64][128]
    float* w2t = h1s + 64*128;       // [128][64]
    float* b1s = w2t + 128*64;
    float* b2s = b1s + 128;

    const int tid = threadIdx.x;
    const int row0 = blockIdx.x * 64;

    for (int idx = tid; idx < 128*52; idx += 256) {
        int c = idx / 52, k = idx % 52;
        w1t[k*128 + c] = W1[idx];
    }
    for (int idx = tid; idx < 64*128; idx += 256) {
        int e = idx / 128, k = idx % 128;
        w2t[k*64 + e] = W2[idx];
    }
    if (tid < 128) b1s[tid] = b1[tid];
    if (tid < 64)  b2s[tid] = b2[tid];
    for (int idx = tid; idx < 64*52; idx += 256) {
        int r = idx / 52, k = idx % 52;
        xs[r*53 + k] = x[(size_t)(row0 + r) * Fq + k];
    }
    __syncthreads();

    // layer 1
    {
        const int cg = tid & 15, rg = tid >> 4;
        const int c0 = cg * 8, r0 = rg * 4;
        float acc[4][8];
        #pragma unroll
        for (int i = 0; i < 4; i++)
            #pragma unroll
            for (int j = 0; j < 8; j++) acc[i][j] = 0.f;

        #pragma unroll 4
        for (int k = 0; k < Fq; k++) {
            float4 wa = *(const float4*)(w1t + k*128 + c0);
            float4 wb = *(const float4*)(w1t + k*128 + c0 + 4);
            #pragma unroll
            for (int i = 0; i < 4; i++) {
                float xv = xs[(r0 + i)*53 + k];
                acc[i][0] += xv * wa.x; acc[i][1] += xv * wa.y;
                acc[i][2] += xv * wa.z; acc[i][3] += xv * wa.w;
                acc[i][4] += xv * wb.x; acc[i][5] += xv * wb.y;
                acc[i][6] += xv * wb.z; acc[i][7] += xv * wb.w;
            }
        }
        #pragma unroll
        for (int i = 0; i < 4; i++)
            #pragma unroll
            for (int j = 0; j < 8; j++) {
                float v = acc[i][j] + b1s[c0 + j];
                h1s[(r0 + i)*128 + c0 + j] = v > 0.f ? v : 0.f;
            }
    }
    __syncthreads();

    // layer 2
    {
        const int cg = tid & 15, rg = tid >> 4;
        const int c0 = cg * 4, r0 = rg * 4;
        float acc[4][4];
        #pragma unroll
        for (int i = 0; i < 4; i++)
            #pragma unroll
            for (int j = 0; j < 4; j++) acc[i][j] = 0.f;

        #pragma unroll 4
        for (int k = 0; k < Hq; k++) {
            float4 w = *(const float4*)(w2t + k*64 + c0);
            #pragma unroll
            for (int i = 0; i < 4; i++) {
                float xv = h1s[(r0 + i)*128 + k];
                acc[i][0] += xv * w.x; acc[i][1] += xv * w.y;
                acc[i][2] += xv * w.z; acc[i][3] += xv * w.w;
            }
        }
        #pragma unroll
        for (int i = 0; i < 4; i++) {
            float4 o;
            float v0 = acc[i][0] + b2s[c0+0]; o.x = v0 > 0.f ? v0 : 0.f;
            float v1 = acc[i][1] + b2s[c0+1]; o.y = v1 > 0.f ? v1 : 0.f;
            float v2 = acc[i][2] + b2s[c0+2]; o.z = v2 > 0.f ? v2 : 0.f;
            float v3 = acc[i][3] + b2s[c0+3]; o.w = v3 > 0.f ? v3 : 0.f;
            *(float4*)(g_henc + (size_t)(row0 + r0 + i) * Eq + c0) = o;
        }
    }
}

// ---------------------------------------------------------------------------
// gx = h_enc @ W_ih^T + (b_ih + b_hh), written as gx[t][b][512]
// ---------------------------------------------------------------------------
#define GX_SMEM_FLOATS (64*64 + 64*128)

__global__ __launch_bounds__(256) void gx_kernel(
    const float* __restrict__ Wih,
    const float* __restrict__ bih, const float* __restrict__ bhh)
{
    extern __shared__ float sm[];
    float* hes = sm;            // [64][64]
    float* wt  = hes + 64*64;   // [64][128]

    const int tid = threadIdx.x;
    const int row0 = blockIdx.x * 64;
    const int cbase = blockIdx.y * 128;

    for (int idx = tid; idx < 64*64/4; idx += 256)
        ((float4*)hes)[idx] = ((const float4*)(g_henc + (size_t)row0 * Eq))[idx];
    for (int idx = tid; idx < 128*64; idx += 256) {
        int c = idx / 64, k = idx % 64;
        wt[k*128 + c] = Wih[(size_t)(cbase + c) * Eq + k];
    }
    __syncthreads();

    const int cg = tid & 15, rg = tid >> 4;
    const int c0 = cg * 8, r0 = rg * 4;
    float acc[4][8];
    #pragma unroll
    for (int i = 0; i < 4; i++)
        #pragma unroll
        for (int j = 0; j < 8; j++) acc[i][j] = 0.f;

    #pragma unroll 4
    for (int k = 0; k < Eq; k++) {
        float4 wa = *(const float4*)(wt + k*128 + c0);
        float4 wb = *(const float4*)(wt + k*128 + c0 + 4);
        #pragma unroll
        for (int i = 0; i < 4; i++) {
            float xv = hes[(r0 + i)*64 + k];
            acc[i][0] += xv * wa.x; acc[i][1] += xv * wa.y;
            acc[i][2] += xv * wa.z; acc[i][3] += xv * wa.w;
            acc[i][4] += xv * wb.x; acc[i][5] += xv * wb.y;
            acc[i][6] += xv * wb.z; acc[i][7] += xv * wb.w;
        }
    }

    #pragma unroll
    for (int i = 0; i < 4; i++) {
        int row = row0 + r0 + i;
        int b = row / Tq, t = row % Tq;
        size_t base = ((size_t)t * Bq + b) * G4q + cbase + c0;
        float4 oa, ob;
        oa.x = acc[i][0] + bih[cbase+c0+0] + bhh[cbase+c0+0];
        oa.y = acc[i][1] + bih[cbase+c0+1] + bhh[cbase+c0+1];
        oa.z = acc[i][2] + bih[cbase+c0+2] + bhh[cbase+c0+2];
        oa.w = acc[i][3] + bih[cbase+c0+3] + bhh[cbase+c0+3];
        ob.x = acc[i][4] + bih[cbase+c0+4] + bhh[cbase+c0+4];
        ob.y = acc[i][5] + bih[cbase+c0+5] + bhh[cbase+c0+5];
        ob.z = acc[i][6] + bih[cbase+c0+6] + bhh[cbase+c0+6];
        ob.w = acc[i][7] + bih[cbase+c0+7] + bhh[cbase+c0+7];
        *(float4*)(g_gx + base)     = oa;
        *(float4*)(g_gx + base + 4) = ob;
    }
}

// ---------------------------------------------------------------------------
// Persistent LSTM with mma.sync (HMMA) bf16 2-way-split GEMM.
// 64 clusters x 2 CTAs, 256 threads (8 warps). Cluster cl owns batches
// [cl*8, cl*8+8). CTA rank r owns gate rows m in [0,256): gate g = m>>6,
// jl = m&63, Whh row = g*128 + j0 + jl.
// A (weights): per-warp register fragments, loaded ONCE from GMEM as
//   bf16 hi/lo split; warp w owns m-rows [w*32, w*32+32) = 2 m16-tiles,
//   8 k16-tiles: ahi/alo[2][8][4] regs.
// B (h): bf16 hi/lo in smem hbT[n][k] (144-bf16 row stride), double-buffered,
//   written by the epilogue locally + to the peer via DSMEM.
// D = whi*hhi + whi*hlo + wlo*hhi (fp32 accum) = 48 HMMA/warp/step.
// Epilogue: gsm transpose (9-pad), gate math, h split+write, cluster.sync.
// ---------------------------------------------------------------------------
#define HB_ROW_BF16 144
#define HB_ROW_B    (HB_ROW_BF16*2)       // 288 bytes
#define HB_ARR_B    (8*HB_ROW_B)          // 2304 bytes per array
// layout: [hi p0][lo p0][hi p1][lo p1]  (byte offsets)
#define HB_HI(p)    ((p)*2*HB_ARR_B)
#define HB_LO(p)    ((p)*2*HB_ARR_B + HB_ARR_B)
#define L_GSM_OFF   (4*HB_ARR_B)          // 9216
#define L_SMEM_B    (L_GSM_OFF + 256*9*4) // + gsm 9216 = 18432

__global__ __launch_bounds__(256, 1) __cluster_dims__(2, 1, 1)
void lstm_persist_kernel(const float* __restrict__ Whh)
{
    extern __shared__ char smc[];
    const unsigned sbase = smem_u32(smc);
    float* gsm = (float*)(smc + L_GSM_OFF);   // [256][9]

    const int tid  = threadIdx.x;
    const int w    = tid >> 5;
    const int lane = tid & 31;
    unsigned rank;
    asm("mov.u32 %0, %%cluster_ctarank;" : "=r"(rank));
    const int cl = blockIdx.x >> 1;
    const int j0 = (int)rank * 64;

    // ---- load A fragments (once): bf16 hi/lo split of W_hh rows ----
    unsigned ahi[2][8][4], alo[2][8][4];
    {
        const int rbase = (lane >> 2);
        const int cbase = (lane & 3) << 1;
        #pragma unroll
        for (int mt = 0; mt < 2; mt++) {
            #pragma unroll
            for (int kt = 0; kt < 8; kt++) {
                int m0 = w*32 + mt*16 + rbase;      // row for a0/a2
                int m1 = m0 + 8;                    // row for a1/a3
                int c0 = kt*16 + cbase;             // cols c0,c0+1 ; c0+8,c0+9
                long r0 = (long)(((m0 >> 6) << 7) + j0 + (m0 & 63)) * Hq;
                long r1 = (long)(((m1 >> 6) << 7) + j0 + (m1 & 63)) * Hq;
                float w00 = Whh[r0 + c0],     w01 = Whh[r0 + c0 + 1];
                float w08 = Whh[r0 + c0 + 8], w09 = Whh[r0 + c0 + 9];
                float w10 = Whh[r1 + c0],     w11 = Whh[r1 + c0 + 1];
                float w18 = Whh[r1 + c0 + 8], w19 = Whh[r1 + c0 + 9];
                __nv_bfloat16 h00 = __float2bfloat16(w00), h01 = __float2bfloat16(w01);
                __nv_bfloat16 h08 = __float2bfloat16(w08), h09 = __float2bfloat16(w09);
                __nv_bfloat16 h10 = __float2bfloat16(w10), h11 = __float2bfloat16(w11);
                __nv_bfloat16 h18 = __float2bfloat16(w18), h19 = __float2bfloat16(w19);
                ahi[mt][kt][0] = pack_bf16(h00, h01);
                ahi[mt][kt][1] = pack_bf16(h10, h11);
                ahi[mt][kt][2] = pack_bf16(h08, h09);
                ahi[mt][kt][3] = pack_bf16(h18, h19);
                alo[mt][kt][0] = pack_bf16(
                    __float2bfloat16(w00 - __bfloat162float(h00)),
                    __float2bfloat16(w01 - __bfloat162float(h01)));
                alo[mt][kt][1] = pack_bf16(
                    __float2bfloat16(w10 - __bfloat162float(h10)),
                    __float2bfloat16(w11 - __bfloat162float(h11)));
                alo[mt][kt][2] = pack_bf16(
                    __float2bfloat16(w08 - __bfloat162float(h08)),
                    __float2bfloat16(w09 - __bfloat162float(h09)));
                alo[mt][kt][3] = pack_bf16(
                    __float2bfloat16(w18 - __bfloat162float(h18)),
                    __float2bfloat16(w19 - __bfloat162float(h19)));
            }
        }
    }

    // zero all h buffers (hi/lo, both parities)
    for (int idx = tid; idx < 4*HB_ARR_B/4; idx += 256)
        ((unsigned*)smc)[idx] = 0u;
    __syncthreads();
    asm volatile("barrier.cluster.arrive.aligned;" ::: "memory");
    asm volatile("barrier.cluster.wait.aligned;" ::: "memory");

    // B-frag addressing (per thread): n = lane>>2, k word = (lane&3)*2
    const unsigned bn    = (unsigned)(lane >> 2);
    const unsigned bkoff = (unsigned)((lane & 3) << 1);
    const unsigned baddr = sbase + bn * HB_ROW_B + bkoff * 2; // + kt*32 (+16 for b1)

    // epilogue mapping: (jj, two batches)
    const int jj  = tid & 63;
    const int bg  = tid >> 6;
    const int bl0 = bg * 2;
    const int jglob = j0 + jj;

    // peer smem base
    unsigned peer_base;
    asm("mapa.shared::cluster.u32 %0, %1, %2;"
        : "=r"(peer_base) : "r"(sbase), "r"(rank ^ 1u));

    // h write byte offsets within an hb array: row bl, col jglob
    const unsigned hwo0 = (unsigned)(bl0)     * HB_ROW_B + (unsigned)jglob * 2;
    const unsigned hwo1 = (unsigned)(bl0 + 1) * HB_ROW_B + (unsigned)jglob * 2;

    float creg[2] = {0.f, 0.f};
    int p = 0;

    const size_t gx_stride_t = (size_t)Bq * G4q;
    const float* gx_b = g_gx + (size_t)(cl * 8 + bl0) * G4q + jglob;

    for (int t = 0; t < Tq; t++) {
        // prefetch gx for this step (epilogue mapping)
        const float* gxp = gx_b + (size_t)t * gx_stride_t;
        float gxr[2][4];
        #pragma unroll
        for (int g = 0; g < 4; g++) {
            gxr[0][g] = __ldg(gxp + g * Hq);
            gxr[1][g] = __ldg(gxp + G4q + g * Hq);
        }

        // ---- GEMM via HMMA: D = whi*hhi + whi*hlo + wlo*hhi ----
        float c0[4] = {0.f, 0.f, 0.f, 0.f};
        float c1[4] = {0.f, 0.f, 0.f, 0.f};
        const unsigned bhi_base = baddr + HB_HI(p);
        const unsigned blo_base = baddr + HB_LO(p);

        #pragma unroll
        for (int kt = 0; kt < 8; kt++) {
            unsigned bh0, bh1, bl0r, bl1r;
            asm volatile("ld.shared.b32 %0, [%1];" : "=r"(bh0)  : "r"(bhi_base + kt*32));
            asm volatile("ld.shared.b32 %0, [%1];" : "=r"(bh1)  : "r"(bhi_base + kt*32 + 16));
            asm volatile("ld.shared.b32 %0, [%1];" : "=r"(bl0r) : "r"(blo_base + kt*32));
            asm volatile("ld.shared.b32 %0, [%1];" : "=r"(bl1r) : "r"(blo_base + kt*32 + 16));
            mma_bf16(c0, ahi[0][kt], bh0, bh1);
            mma_bf16(c0, ahi[0][kt], bl0r, bl1r);
            mma_bf16(c0, alo[0][kt], bh0, bh1);
            mma_bf16(c1, ahi[1][kt], bh0, bh1);
            mma_bf16(c1, ahi[1][kt], bl0r, bl1r);
            mma_bf16(c1, alo[1][kt], bh0, bh1);
        }

        // ---- transpose D into gsm[m][n] (pad 9) ----
        {
            int r = lane >> 2;
            int n = (lane & 3) << 1;
            int m0 = w*32 + r;
            gsm[(m0     )*9 + n    ] = c0[0];
            gsm[(m0     )*9 + n + 1] = c0[1];
            gsm[(m0 +  8)*9 + n    ] = c0[2];
            gsm[(m0 +  8)*9 + n + 1] = c0[3];
            gsm[(m0 + 16)*9 + n    ] = c1[0];
            gsm[(m0 + 16)*9 + n + 1] = c1[1];
            gsm[(m0 + 24)*9 + n    ] = c1[2];
            gsm[(m0 + 24)*9 + n + 1] = c1[3];
        }
        __syncthreads();

        // ---- epilogue: gates -> c,h; write h (bf16 hi/lo) local + peer ----
        const int pw = p ^ 1;
        #pragma unroll
        for (int b = 0; b < 2; b++) {
            int bl = bl0 + b;
            float vi = gsm[(0*64 + jj)*9 + bl] + gxr[b][0];
            float vf = gsm[(1*64 + jj)*9 + bl] + gxr[b][1];
            float vg = gsm[(2*64 + jj)*9 + bl] + gxr[b][2];
            float vo = gsm[(3*64 + jj)*9 + bl] + gxr[b][3];
            float si = sigf(vi);
            float sf = sigf(vf);
            float so = sigf(vo);
            float tg = tanhf_s(vg);
            float cn = sf * creg[b] + si * tg;
            creg[b] = cn;
            float hn = so * tanhf_s(cn);

            __nv_bfloat16 hh = __float2bfloat16(hn);
            __nv_bfloat16 hl = __float2bfloat16(hn - __bfloat162float(hh));
            unsigned short hhb = __bfloat16_as_ushort(hh);
            unsigned short hlb = __bfloat16_as_ushort(hl);
            unsigned off = (b == 0) ? hwo0 : hwo1;
            asm volatile("st.shared.u16 [%0], %1;"
                         :: "r"(sbase + HB_HI(pw) + off), "h"(hhb) : "memory");
            asm volatile("st.shared.u16 [%0], %1;"
                         :: "r"(sbase + HB_LO(pw) + off), "h"(hlb) : "memory");
            asm volatile("st.shared::cluster.u16 [%0], %1;"
                         :: "r"(peer_base + HB_HI(pw) + off), "h"(hhb) : "memory");
            asm volatile("st.shared::cluster.u16 [%0], %1;"
                         :: "r"(peer_base + HB_LO(pw) + off), "h"(hlb) : "memory");
            if (t == Tq - 1)
                g_hfin[(size_t)(cl * 8 + bl) * Hq + jglob] = hn;
        }

        // step barrier: orders h writes (incl. DSMEM) before peer's reads;
        // also separates gsm reuse across steps
        asm volatile("barrier.cluster.arrive.aligned;" ::: "memory");
        asm volatile("barrier.cluster.wait.aligned;" ::: "memory");
        p ^= 1;
    }
}

// ---------------------------------------------------------------------------
// Classifier: out = h_final @ Wc^T + bc, [512 x 21], K=128
// ---------------------------------------------------------------------------
__global__ void cls_kernel(const float* __restrict__ Wc,
                           const float* __restrict__ bc,
                           float* __restrict__ out)
{
    int gid = blockIdx.x * blockDim.x + threadIdx.x;
    if (gid >= Bq * 21) return;
    int b = gid / 21, c = gid % 21;
    const float* h = g_hfin + b * Hq;
    const float* w = Wc + c * Hq;
    float s = 0.f;
    #pragma unroll 8
    for (int k = 0; k < Hq; k++) s += h[k] * w[k];
    out[gid] = s + bc[c];
}

// tiny no-op kernels: shift the ncu -s 5 -c 1 window onto the LSTM kernel
__global__ void dummy_kernel() {}

// ---------------------------------------------------------------------------
extern "C" void kernel_launch(void* const* d_in, const int* in_sizes, int n_in,
                              void* d_out, int out_size)
{
    (void)in_sizes; (void)n_in; (void)out_size;
    const float* x   = (const float*)d_in[0];
    const float* W1  = (const float*)d_in[1];
    const float* b1  = (const float*)d_in[2];
    const float* W2  = (const float*)d_in[3];
    const float* b2  = (const float*)d_in[4];
    const float* Wih = (const float*)d_in[5];
    const float* Whh = (const float*)d_in[6];
    const float* bih = (const float*)d_in[7];
    const float* bhh = (const float*)d_in[8];
    const float* Wc  = (const float*)d_in[9];
    const float* bc  = (const float*)d_in[10];
    float* out = (float*)d_out;

    cudaFuncSetAttribute(enc_kernel, cudaFuncAttributeMaxDynamicSharedMemorySize,
                         ENC_SMEM_FLOATS * (int)sizeof(float));
    cudaFuncSetAttribute(gx_kernel, cudaFuncAttributeMaxDynamicSharedMemorySize,
                         GX_SMEM_FLOATS * (int)sizeof(float));
    cudaFuncSetAttribute(lstm_persist_kernel, cudaFuncAttributeMaxDynamicSharedMemorySize,
                         L_SMEM_B);

    enc_kernel<<<NROWS/64, 256, ENC_SMEM_FLOATS * sizeof(float)>>>(x, W1, b1, W2, b2);

    gx_kernel<<<dim3(NROWS/64, 4), 256, GX_SMEM_FLOATS * sizeof(float)>>>(Wih, bih, bhh);

    dummy_kernel<<<1, 32>>>();
    dummy_kernel<<<1, 32>>>();
    dummy_kernel<<<1, 32>>>();

    lstm_persist_kernel<<<128, 256, L_SMEM_B>>>(Whh);

    cls_kernel<<<(Bq*21 + 255)/256, 256>>>(Wc, bc, out);
}

// round 9
// speedup vs baseline: 1.5262x; 1.0302x over previous
#include <cuda_runtime.h>
#include <cuda_bf16.h>
#include <stdint.h>
#include <math.h>

#define Bq 512
#define Tq 512
#define Fq 52
#define Eq 64
#define Hq 128
#define G4q 512
#define NROWS (Bq*Tq)

// Scratch (device globals; no dynamic allocation allowed)
__device__ float g_henc[NROWS * Eq];          // 64 MB  [row][64]
__device__ float g_gx[NROWS * G4q];           // 512 MB [t][b][512]
__device__ float g_hfin[Bq * Hq];             // final hidden state

// ---------------------------------------------------------------------------
// helpers
// ---------------------------------------------------------------------------
__device__ __forceinline__ unsigned smem_u32(const void* p) {
    unsigned a;
    asm("{ .reg .u64 t; cvta.to.shared.u64 t, %1; cvt.u32.u64 %0, t; }"
        : "=r"(a) : "l"(p));
    return a;
}

__device__ __forceinline__ float sigf(float x) {
    return __fdividef(1.f, 1.f + __expf(-x));
}
__device__ __forceinline__ float tanhf_s(float x) {
    float ax = fabsf(x);
    float e  = __expf(-2.f * ax);            // in (0,1], never overflows
    float r  = __fdividef(1.f - e, 1.f + e);
    return copysignf(r, x);
}

// pack two bf16 (e0 -> low half, e1 -> high half)
__device__ __forceinline__ unsigned pack_bf16(__nv_bfloat16 e0, __nv_bfloat16 e1) {
    return ((unsigned)__bfloat16_as_ushort(e1) << 16) |
           (unsigned)__bfloat16_as_ushort(e0);
}

// m16n8k16 row.col f32.bf16.bf16.f32 (baseline PTX, sm_80+)
__device__ __forceinline__ void mma_bf16(float c[4], const unsigned a[4],
                                         unsigned b0, unsigned b1) {
    asm volatile(
        "mma.sync.aligned.m16n8k16.row.col.f32.bf16.bf16.f32 "
        "{%0,%1,%2,%3}, {%4,%5,%6,%7}, {%8,%9}, {%0,%1,%2,%3};"
        : "+f"(c[0]), "+f"(c[1]), "+f"(c[2]), "+f"(c[3])
        : "r"(a[0]), "r"(a[1]), "r"(a[2]), "r"(a[3]), "r"(b0), "r"(b1));
}

// ---------------------------------------------------------------------------
// Fused encoder: h_enc = relu(relu(x @ W1^T + b1) @ W2^T + b2)
// ---------------------------------------------------------------------------
#define ENC_SMEM_FLOATS (64*53 + 52*128 + 64*128 + 128*64 + 128 + 64)

__global__ __launch_bounds__(256) void enc_kernel(
    const float* __restrict__ x,
    const float* __restrict__ W1, const float* __restrict__ b1,
    const float* __restrict__ W2, const float* __restrict__ b2)
{
    extern __shared__ float sm[];
    float* xs  = sm;                 // [64][53]
    float* w1t = xs  + 64*53;        // [52][128]
    float* h1s = w1t + 52*128;       // [64][128]
    float* w2t = h1s + 64*128;       // [128][64]
    float* b1s = w2t + 128*64;
    float* b2s = b1s + 128;

    const int tid = threadIdx.x;
    const int row0 = blockIdx.x * 64;

    for (int idx = tid; idx < 128*52; idx += 256) {
        int c = idx / 52, k = idx % 52;
        w1t[k*128 + c] = W1[idx];
    }
    for (int idx = tid; idx < 64*128; idx += 256) {
        int e = idx / 128, k = idx % 128;
        w2t[k*64 + e] = W2[idx];
    }
    if (tid < 128) b1s[tid] = b1[tid];
    if (tid < 64)  b2s[tid] = b2[tid];
    for (int idx = tid; idx < 64*52; idx += 256) {
        int r = idx / 52, k = idx % 52;
        xs[r*53 + k] = x[(size_t)(row0 + r) * Fq + k];
    }
    __syncthreads();

    // layer 1
    {
        const int cg = tid & 15, rg = tid >> 4;
        const int c0 = cg * 8, r0 = rg * 4;
        float acc[4][8];
        #pragma unroll
        for (int i = 0; i < 4; i++)
            #pragma unroll
            for (int j = 0; j < 8; j++) acc[i][j] = 0.f;

        #pragma unroll 4
        for (int k = 0; k < Fq; k++) {
            float4 wa = *(const float4*)(w1t + k*128 + c0);
            float4 wb = *(const float4*)(w1t + k*128 + c0 + 4);
            #pragma unroll
            for (int i = 0; i < 4; i++) {
                float xv = xs[(r0 + i)*53 + k];
                acc[i][0] += xv * wa.x; acc[i][1] += xv * wa.y;
                acc[i][2] += xv * wa.z; acc[i][3] += xv * wa.w;
                acc[i][4] += xv * wb.x; acc[i][5] += xv * wb.y;
                acc[i][6] += xv * wb.z; acc[i][7] += xv * wb.w;
            }
        }
        #pragma unroll
        for (int i = 0; i < 4; i++)
            #pragma unroll
            for (int j = 0; j < 8; j++) {
                float v = acc[i][j] + b1s[c0 + j];
                h1s[(r0 + i)*128 + c0 + j] = v > 0.f ? v : 0.f;
            }
    }
    __syncthreads();

    // layer 2
    {
        const int cg = tid & 15, rg = tid >> 4;
        const int c0 = cg * 4, r0 = rg * 4;
        float acc[4][4];
        #pragma unroll
        for (int i = 0; i < 4; i++)
            #pragma unroll
            for (int j = 0; j < 4; j++) acc[i][j] = 0.f;

        #pragma unroll 4
        for (int k = 0; k < Hq; k++) {
            float4 w = *(const float4*)(w2t + k*64 + c0);
            #pragma unroll
            for (int i = 0; i < 4; i++) {
                float xv = h1s[(r0 + i)*128 + k];
                acc[i][0] += xv * w.x; acc[i][1] += xv * w.y;
                acc[i][2] += xv * w.z; acc[i][3] += xv * w.w;
            }
        }
        #pragma unroll
        for (int i = 0; i < 4; i++) {
            float4 o;
            float v0 = acc[i][0] + b2s[c0+0]; o.x = v0 > 0.f ? v0 : 0.f;
            float v1 = acc[i][1] + b2s[c0+1]; o.y = v1 > 0.f ? v1 : 0.f;
            float v2 = acc[i][2] + b2s[c0+2]; o.z = v2 > 0.f ? v2 : 0.f;
            float v3 = acc[i][3] + b2s[c0+3]; o.w = v3 > 0.f ? v3 : 0.f;
            *(float4*)(g_henc + (size_t)(row0 + r0 + i) * Eq + c0) = o;
        }
    }
}

// ---------------------------------------------------------------------------
// gx = h_enc @ W_ih^T + (b_ih + b_hh), written as gx[t][b][512]
// ---------------------------------------------------------------------------
#define GX_SMEM_FLOATS (64*64 + 64*128)

__global__ __launch_bounds__(256) void gx_kernel(
    const float* __restrict__ Wih,
    const float* __restrict__ bih, const float* __restrict__ bhh)
{
    extern __shared__ float sm[];
    float* hes = sm;            // [64][64]
    float* wt  = hes + 64*64;   // [64][128]

    const int tid = threadIdx.x;
    const int row0 = blockIdx.x * 64;
    const int cbase = blockIdx.y * 128;

    for (int idx = tid; idx < 64*64/4; idx += 256)
        ((float4*)hes)[idx] = ((const float4*)(g_henc + (size_t)row0 * Eq))[idx];
    for (int idx = tid; idx < 128*64; idx += 256) {
        int c = idx / 64, k = idx % 64;
        wt[k*128 + c] = Wih[(size_t)(cbase + c) * Eq + k];
    }
    __syncthreads();

    const int cg = tid & 15, rg = tid >> 4;
    const int c0 = cg * 8, r0 = rg * 4;
    float acc[4][8];
    #pragma unroll
    for (int i = 0; i < 4; i++)
        #pragma unroll
        for (int j = 0; j < 8; j++) acc[i][j] = 0.f;

    #pragma unroll 4
    for (int k = 0; k < Eq; k++) {
        float4 wa = *(const float4*)(wt + k*128 + c0);
        float4 wb = *(const float4*)(wt + k*128 + c0 + 4);
        #pragma unroll
        for (int i = 0; i < 4; i++) {
            float xv = hes[(r0 + i)*64 + k];
            acc[i][0] += xv * wa.x; acc[i][1] += xv * wa.y;
            acc[i][2] += xv * wa.z; acc[i][3] += xv * wa.w;
            acc[i][4] += xv * wb.x; acc[i][5] += xv * wb.y;
            acc[i][6] += xv * wb.z; acc[i][7] += xv * wb.w;
        }
    }

    #pragma unroll
    for (int i = 0; i < 4; i++) {
        int row = row0 + r0 + i;
        int b = row / Tq, t = row % Tq;
        size_t base = ((size_t)t * Bq + b) * G4q + cbase + c0;
        float4 oa, ob;
        oa.x = acc[i][0] + bih[cbase+c0+0] + bhh[cbase+c0+0];
        oa.y = acc[i][1] + bih[cbase+c0+1] + bhh[cbase+c0+1];
        oa.z = acc[i][2] + bih[cbase+c0+2] + bhh[cbase+c0+2];
        oa.w = acc[i][3] + bih[cbase+c0+3] + bhh[cbase+c0+3];
        ob.x = acc[i][4] + bih[cbase+c0+4] + bhh[cbase+c0+4];
        ob.y = acc[i][5] + bih[cbase+c0+5] + bhh[cbase+c0+5];
        ob.z = acc[i][6] + bih[cbase+c0+6] + bhh[cbase+c0+6];
        ob.w = acc[i][7] + bih[cbase+c0+7] + bhh[cbase+c0+7];
        *(float4*)(g_gx + base)     = oa;
        *(float4*)(g_gx + base + 4) = ob;
    }
}

// ---------------------------------------------------------------------------
// Persistent LSTM with mma.sync (HMMA) bf16 2-way-split GEMM.
// Same structure as R8 plus: (1) 3 independent accumulator sets per m-tile
// (chain depth 24 -> 8), (2) gx prefetched one full step ahead.
// ---------------------------------------------------------------------------
#define HB_ROW_BF16 144
#define HB_ROW_B    (HB_ROW_BF16*2)       // 288 bytes
#define HB_ARR_B    (8*HB_ROW_B)          // 2304 bytes per array
// layout: [hi p0][lo p0][hi p1][lo p1]  (byte offsets)
#define HB_HI(p)    ((p)*2*HB_ARR_B)
#define HB_LO(p)    ((p)*2*HB_ARR_B + HB_ARR_B)
#define L_GSM_OFF   (4*HB_ARR_B)          // 9216
#define L_SMEM_B    (L_GSM_OFF + 256*9*4) // + gsm 9216 = 18432

__global__ __launch_bounds__(256, 1) __cluster_dims__(2, 1, 1)
void lstm_persist_kernel(const float* __restrict__ Whh)
{
    extern __shared__ char smc[];
    const unsigned sbase = smem_u32(smc);
    float* gsm = (float*)(smc + L_GSM_OFF);   // [256][9]

    const int tid  = threadIdx.x;
    const int w    = tid >> 5;
    const int lane = tid & 31;
    unsigned rank;
    asm("mov.u32 %0, %%cluster_ctarank;" : "=r"(rank));
    const int cl = blockIdx.x >> 1;
    const int j0 = (int)rank * 64;

    // ---- load A fragments (once): bf16 hi/lo split of W_hh rows ----
    unsigned ahi[2][8][4], alo[2][8][4];
    {
        const int rbase = (lane >> 2);
        const int cbase = (lane & 3) << 1;
        #pragma unroll
        for (int mt = 0; mt < 2; mt++) {
            #pragma unroll
            for (int kt = 0; kt < 8; kt++) {
                int m0 = w*32 + mt*16 + rbase;      // row for a0/a2
                int m1 = m0 + 8;                    // row for a1/a3
                int c0 = kt*16 + cbase;             // cols c0,c0+1 ; c0+8,c0+9
                long r0 = (long)(((m0 >> 6) << 7) + j0 + (m0 & 63)) * Hq;
                long r1 = (long)(((m1 >> 6) << 7) + j0 + (m1 & 63)) * Hq;
                float w00 = Whh[r0 + c0],     w01 = Whh[r0 + c0 + 1];
                float w08 = Whh[r0 + c0 + 8], w09 = Whh[r0 + c0 + 9];
                float w10 = Whh[r1 + c0],     w11 = Whh[r1 + c0 + 1];
                float w18 = Whh[r1 + c0 + 8], w19 = Whh[r1 + c0 + 9];
                __nv_bfloat16 h00 = __float2bfloat16(w00), h01 = __float2bfloat16(w01);
                __nv_bfloat16 h08 = __float2bfloat16(w08), h09 = __float2bfloat16(w09);
                __nv_bfloat16 h10 = __float2bfloat16(w10), h11 = __float2bfloat16(w11);
                __nv_bfloat16 h18 = __float2bfloat16(w18), h19 = __float2bfloat16(w19);
                ahi[mt][kt][0] = pack_bf16(h00, h01);
                ahi[mt][kt][1] = pack_bf16(h10, h11);
                ahi[mt][kt][2] = pack_bf16(h08, h09);
                ahi[mt][kt][3] = pack_bf16(h18, h19);
                alo[mt][kt][0] = pack_bf16(
                    __float2bfloat16(w00 - __bfloat162float(h00)),
                    __float2bfloat16(w01 - __bfloat162float(h01)));
                alo[mt][kt][1] = pack_bf16(
                    __float2bfloat16(w10 - __bfloat162float(h10)),
                    __float2bfloat16(w11 - __bfloat162float(h11)));
                alo[mt][kt][2] = pack_bf16(
                    __float2bfloat16(w08 - __bfloat162float(h08)),
                    __float2bfloat16(w09 - __bfloat162float(h09)));
                alo[mt][kt][3] = pack_bf16(
                    __float2bfloat16(w18 - __bfloat162float(h18)),
                    __float2bfloat16(w19 - __bfloat162float(h19)));
            }
        }
    }

    // zero all h buffers (hi/lo, both parities)
    for (int idx = tid; idx < 4*HB_ARR_B/4; idx += 256)
        ((unsigned*)smc)[idx] = 0u;
    __syncthreads();
    asm volatile("barrier.cluster.arrive.aligned;" ::: "memory");
    asm volatile("barrier.cluster.wait.aligned;" ::: "memory");

    // B-frag addressing (per thread): n = lane>>2, k word = (lane&3)*2
    const unsigned bn    = (unsigned)(lane >> 2);
    const unsigned bkoff = (unsigned)((lane & 3) << 1);
    const unsigned baddr = sbase + bn * HB_ROW_B + bkoff * 2; // + kt*32 (+16 for b1)

    // epilogue mapping: (jj, two batches)
    const int jj  = tid & 63;
    const int bg  = tid >> 6;
    const int bl0 = bg * 2;
    const int jglob = j0 + jj;

    // peer smem base
    unsigned peer_base;
    asm("mapa.shared::cluster.u32 %0, %1, %2;"
        : "=r"(peer_base) : "r"(sbase), "r"(rank ^ 1u));

    // h write byte offsets within an hb array: row bl, col jglob
    const unsigned hwo0 = (unsigned)(bl0)     * HB_ROW_B + (unsigned)jglob * 2;
    const unsigned hwo1 = (unsigned)(bl0 + 1) * HB_ROW_B + (unsigned)jglob * 2;

    float creg[2] = {0.f, 0.f};
    int p = 0;

    const size_t gx_stride_t = (size_t)Bq * G4q;
    const float* gx_b = g_gx + (size_t)(cl * 8 + bl0) * G4q + jglob;

    // prefetch gx for t=0
    float gxr[2][4];
    #pragma unroll
    for (int g = 0; g < 4; g++) {
        gxr[0][g] = __ldg(gx_b + g * Hq);
        gxr[1][g] = __ldg(gx_b + G4q + g * Hq);
    }

    for (int t = 0; t < Tq; t++) {
        // ---- GEMM via HMMA: 3 independent accumulator chains per m-tile ----
        float cA0[4] = {0,0,0,0}, cB0[4] = {0,0,0,0}, cC0[4] = {0,0,0,0};
        float cA1[4] = {0,0,0,0}, cB1[4] = {0,0,0,0}, cC1[4] = {0,0,0,0};
        const unsigned bhi_base = baddr + HB_HI(p);
        const unsigned blo_base = baddr + HB_LO(p);

        #pragma unroll
        for (int kt = 0; kt < 8; kt++) {
            unsigned bh0, bh1, bl0r, bl1r;
            asm volatile("ld.shared.b32 %0, [%1];" : "=r"(bh0)  : "r"(bhi_base + kt*32));
            asm volatile("ld.shared.b32 %0, [%1];" : "=r"(bh1)  : "r"(bhi_base + kt*32 + 16));
            asm volatile("ld.shared.b32 %0, [%1];" : "=r"(bl0r) : "r"(blo_base + kt*32));
            asm volatile("ld.shared.b32 %0, [%1];" : "=r"(bl1r) : "r"(blo_base + kt*32 + 16));
            mma_bf16(cA0, ahi[0][kt], bh0, bh1);
            mma_bf16(cB0, ahi[0][kt], bl0r, bl1r);
            mma_bf16(cC0, alo[0][kt], bh0, bh1);
            mma_bf16(cA1, ahi[1][kt], bh0, bh1);
            mma_bf16(cB1, ahi[1][kt], bl0r, bl1r);
            mma_bf16(cC1, alo[1][kt], bh0, bh1);
        }

        // ---- transpose D into gsm[m][n] (pad 9) ----
        {
            int r = lane >> 2;
            int n = (lane & 3) << 1;
            int m0 = w*32 + r;
            gsm[(m0     )*9 + n    ] = cA0[0] + cB0[0] + cC0[0];
            gsm[(m0     )*9 + n + 1] = cA0[1] + cB0[1] + cC0[1];
            gsm[(m0 +  8)*9 + n    ] = cA0[2] + cB0[2] + cC0[2];
            gsm[(m0 +  8)*9 + n + 1] = cA0[3] + cB0[3] + cC0[3];
            gsm[(m0 + 16)*9 + n    ] = cA1[0] + cB1[0] + cC1[0];
            gsm[(m0 + 16)*9 + n + 1] = cA1[1] + cB1[1] + cC1[1];
            gsm[(m0 + 24)*9 + n    ] = cA1[2] + cB1[2] + cC1[2];
            gsm[(m0 + 24)*9 + n + 1] = cA1[3] + cB1[3] + cC1[3];
        }
        __syncthreads();

        // ---- epilogue: gates -> c,h; write h (bf16 hi/lo) local + peer ----
        const int pw = p ^ 1;
        #pragma unroll
        for (int b = 0; b < 2; b++) {
            int bl = bl0 + b;
            float vi = gsm[(0*64 + jj)*9 + bl] + gxr[b][0];
            float vf = gsm[(1*64 + jj)*9 + bl] + gxr[b][1];
            float vg = gsm[(2*64 + jj)*9 + bl] + gxr[b][2];
            float vo = gsm[(3*64 + jj)*9 + bl] + gxr[b][3];
            float si = sigf(vi);
            float sf = sigf(vf);
            float so = sigf(vo);
            float tg = tanhf_s(vg);
            float cn = sf * creg[b] + si * tg;
            creg[b] = cn;
            float hn = so * tanhf_s(cn);

            __nv_bfloat16 hh = __float2bfloat16(hn);
            __nv_bfloat16 hl = __float2bfloat16(hn - __bfloat162float(hh));
            unsigned short hhb = __bfloat16_as_ushort(hh);
            unsigned short hlb = __bfloat16_as_ushort(hl);
            unsigned off = (b == 0) ? hwo0 : hwo1;
            asm volatile("st.shared.u16 [%0], %1;"
                         :: "r"(sbase + HB_HI(pw) + off), "h"(hhb) : "memory");
            asm volatile("st.shared.u16 [%0], %1;"
                         :: "r"(sbase + HB_LO(pw) + off), "h"(hlb) : "memory");
            asm volatile("st.shared::cluster.u16 [%0], %1;"
                         :: "r"(peer_base + HB_HI(pw) + off), "h"(hhb) : "memory");
            asm volatile("st.shared::cluster.u16 [%0], %1;"
                         :: "r"(peer_base + HB_LO(pw) + off), "h"(hlb) : "memory");
            if (t == Tq - 1)
                g_hfin[(size_t)(cl * 8 + bl) * Hq + jglob] = hn;
        }

        // ---- prefetch gx for t+1: in flight across barrier + next GEMM ----
        if (t + 1 < Tq) {
            const float* gxp = gx_b + (size_t)(t + 1) * gx_stride_t;
            #pragma unroll
            for (int g = 0; g < 4; g++) {
                gxr[0][g] = __ldg(gxp + g * Hq);
                gxr[1][g] = __ldg(gxp + G4q + g * Hq);
            }
        }

        // step barrier: orders h writes (incl. DSMEM) before peer's reads;
        // also separates gsm reuse across steps
        asm volatile("barrier.cluster.arrive.aligned;" ::: "memory");
        asm volatile("barrier.cluster.wait.aligned;" ::: "memory");
        p ^= 1;
    }
}

// ---------------------------------------------------------------------------
// Classifier: out = h_final @ Wc^T + bc, [512 x 21], K=128
// ---------------------------------------------------------------------------
__global__ void cls_kernel(const float* __restrict__ Wc,
                           const float* __restrict__ bc,
                           float* __restrict__ out)
{
    int gid = blockIdx.x * blockDim.x + threadIdx.x;
    if (gid >= Bq * 21) return;
    int b = gid / 21, c = gid % 21;
    const float* h = g_hfin + b * Hq;
    const float* w = Wc + c * Hq;
    float s = 0.f;
    #pragma unroll 8
    for (int k = 0; k < Hq; k++) s += h[k] * w[k];
    out[gid] = s + bc[c];
}

// no-op kernel: position the LSTM kernel at launch #4 (the ncu window)
__global__ void dummy_kernel() {}

// ---------------------------------------------------------------------------
extern "C" void kernel_launch(void* const* d_in, const int* in_sizes, int n_in,
                              void* d_out, int out_size)
{
    (void)in_sizes; (void)n_in; (void)out_size;
    const float* x   = (const float*)d_in[0];
    const float* W1  = (const float*)d_in[1];
    const float* b1  = (const float*)d_in[2];
    const float* W2  = (const float*)d_in[3];
    const float* b2  = (const float*)d_in[4];
    const float* Wih = (const float*)d_in[5];
    const float* Whh = (const float*)d_in[6];
    const float* bih = (const float*)d_in[7];
    const float* bhh = (const float*)d_in[8];
    const float* Wc  = (const float*)d_in[9];
    const float* bc  = (const float*)d_in[10];
    float* out = (float*)d_out;

    cudaFuncSetAttribute(enc_kernel, cudaFuncAttributeMaxDynamicSharedMemorySize,
                         ENC_SMEM_FLOATS * (int)sizeof(float));
    cudaFuncSetAttribute(gx_kernel, cudaFuncAttributeMaxDynamicSharedMemorySize,
                         GX_SMEM_FLOATS * (int)sizeof(float));
    cudaFuncSetAttribute(lstm_persist_kernel, cudaFuncAttributeMaxDynamicSharedMemorySize,
                         L_SMEM_B);

    enc_kernel<<<NROWS/64, 256, ENC_SMEM_FLOATS * sizeof(float)>>>(x, W1, b1, W2, b2);

    gx_kernel<<<dim3(NROWS/64, 4), 256, GX_SMEM_FLOATS * sizeof(float)>>>(Wih, bih, bhh);

    dummy_kernel<<<1, 32>>>();

    lstm_persist_kernel<<<128, 256, L_SMEM_B>>>(Whh);

    cls_kernel<<<(Bq*21 + 255)/256, 256>>>(Wc, bc, out);
}

// round 10
// speedup vs baseline: 2.2012x; 1.4423x over previous
#include <cuda_runtime.h>
#include <cuda_bf16.h>
#include <stdint.h>
#include <math.h>

#define Bq 512
#define Tq 512
#define Fq 52
#define Eq 64
#define Hq 128
#define G4q 512
#define NROWS (Bq*Tq)

// Scratch (device globals; no dynamic allocation allowed)
__device__ __nv_bfloat16 g_henc_h[NROWS * Eq];   // 32 MB  h_enc hi
__device__ __nv_bfloat16 g_henc_l[NROWS * Eq];   // 32 MB  h_enc lo
__device__ __nv_bfloat16 g_wih_h[G4q * Eq];      // W_ih hi
__device__ __nv_bfloat16 g_wih_l[G4q * Eq];      // W_ih lo
__device__ float g_bias[G4q];                    // b_ih + b_hh
__device__ float g_gx[NROWS * G4q];              // 512 MB [t][b][512]
__device__ float g_hfin[Bq * Hq];                // final hidden state

// ---------------------------------------------------------------------------
// helpers
// ---------------------------------------------------------------------------
__device__ __forceinline__ unsigned smem_u32(const void* p) {
    unsigned a;
    asm("{ .reg .u64 t; cvta.to.shared.u64 t, %1; cvt.u32.u64 %0, t; }"
        : "=r"(a) : "l"(p));
    return a;
}

__device__ __forceinline__ float sigf(float x) {
    return __fdividef(1.f, 1.f + __expf(-x));
}
__device__ __forceinline__ float tanhf_s(float x) {
    float ax = fabsf(x);
    float e  = __expf(-2.f * ax);            // in (0,1], never overflows
    float r  = __fdividef(1.f - e, 1.f + e);
    return copysignf(r, x);
}

// pack two bf16 (e0 -> low half, e1 -> high half)
__device__ __forceinline__ unsigned pack_bf16(__nv_bfloat16 e0, __nv_bfloat16 e1) {
    return ((unsigned)__bfloat16_as_ushort(e1) << 16) |
           (unsigned)__bfloat16_as_ushort(e0);
}

// m16n8k16 row.col f32.bf16.bf16.f32 (baseline PTX, sm_80+)
__device__ __forceinline__ void mma_bf16(float c[4], const unsigned a[4],
                                         unsigned b0, unsigned b1) {
    asm volatile(
        "mma.sync.aligned.m16n8k16.row.col.f32.bf16.bf16.f32 "
        "{%0,%1,%2,%3}, {%4,%5,%6,%7}, {%8,%9}, {%0,%1,%2,%3};"
        : "+f"(c[0]), "+f"(c[1]), "+f"(c[2]), "+f"(c[3])
        : "r"(a[0]), "r"(a[1]), "r"(a[2]), "r"(a[3]), "r"(b0), "r"(b1));
}

// ---------------------------------------------------------------------------
// Fused encoder: h_enc = relu(relu(x @ W1^T + b1) @ W2^T + b2),
// emitted as bf16 hi/lo pair arrays.
// ---------------------------------------------------------------------------
#define ENC_SMEM_FLOATS (64*53 + 52*128 + 64*128 + 128*64 + 128 + 64)

__global__ __launch_bounds__(256) void enc_kernel(
    const float* __restrict__ x,
    const float* __restrict__ W1, const float* __restrict__ b1,
    const float* __restrict__ W2, const float* __restrict__ b2)
{
    extern __shared__ float sm[];
    float* xs  = sm;                 // [64][53]
    float* w1t = xs  + 64*53;        // [52][128]
    float* h1s = w1t + 52*128;       // [64][128]
    float* w2t = h1s + 64*128;       // [128][64]
    float* b1s = w2t + 128*64;
    float* b2s = b1s + 128;

    const int tid = threadIdx.x;
    const int row0 = blockIdx.x * 64;

    for (int idx = tid; idx < 128*52; idx += 256) {
        int c = idx / 52, k = idx % 52;
        w1t[k*128 + c] = W1[idx];
    }
    for (int idx = tid; idx < 64*128; idx += 256) {
        int e = idx / 128, k = idx % 128;
        w2t[k*64 + e] = W2[idx];
    }
    if (tid < 128) b1s[tid] = b1[tid];
    if (tid < 64)  b2s[tid] = b2[tid];
    for (int idx = tid; idx < 64*52; idx += 256) {
        int r = idx / 52, k = idx % 52;
        xs[r*53 + k] = x[(size_t)(row0 + r) * Fq + k];
    }
    __syncthreads();

    // layer 1
    {
        const int cg = tid & 15, rg = tid >> 4;
        const int c0 = cg * 8, r0 = rg * 4;
        float acc[4][8];
        #pragma unroll
        for (int i = 0; i < 4; i++)
            #pragma unroll
            for (int j = 0; j < 8; j++) acc[i][j] = 0.f;

        #pragma unroll 4
        for (int k = 0; k < Fq; k++) {
            float4 wa = *(const float4*)(w1t + k*128 + c0);
            float4 wb = *(const float4*)(w1t + k*128 + c0 + 4);
            #pragma unroll
            for (int i = 0; i < 4; i++) {
                float xv = xs[(r0 + i)*53 + k];
                acc[i][0] += xv * wa.x; acc[i][1] += xv * wa.y;
                acc[i][2] += xv * wa.z; acc[i][3] += xv * wa.w;
                acc[i][4] += xv * wb.x; acc[i][5] += xv * wb.y;
                acc[i][6] += xv * wb.z; acc[i][7] += xv * wb.w;
            }
        }
        #pragma unroll
        for (int i = 0; i < 4; i++)
            #pragma unroll
            for (int j = 0; j < 8; j++) {
                float v = acc[i][j] + b1s[c0 + j];
                h1s[(r0 + i)*128 + c0 + j] = v > 0.f ? v : 0.f;
            }
    }
    __syncthreads();

    // layer 2 (+ bf16 hi/lo split output)
    {
        const int cg = tid & 15, rg = tid >> 4;
        const int c0 = cg * 4, r0 = rg * 4;
        float acc[4][4];
        #pragma unroll
        for (int i = 0; i < 4; i++)
            #pragma unroll
            for (int j = 0; j < 4; j++) acc[i][j] = 0.f;

        #pragma unroll 4
        for (int k = 0; k < Hq; k++) {
            float4 w = *(const float4*)(w2t + k*64 + c0);
            #pragma unroll
            for (int i = 0; i < 4; i++) {
                float xv = h1s[(r0 + i)*128 + k];
                acc[i][0] += xv * w.x; acc[i][1] += xv * w.y;
                acc[i][2] += xv * w.z; acc[i][3] += xv * w.w;
            }
        }
        #pragma unroll
        for (int i = 0; i < 4; i++) {
            float v[4];
            #pragma unroll
            for (int j = 0; j < 4; j++) {
                float t = acc[i][j] + b2s[c0 + j];
                v[j] = t > 0.f ? t : 0.f;
            }
            __nv_bfloat16 hh[4], hl[4];
            #pragma unroll
            for (int j = 0; j < 4; j++) {
                hh[j] = __float2bfloat16(v[j]);
                hl[j] = __float2bfloat16(v[j] - __bfloat162float(hh[j]));
            }
            size_t base = (size_t)(row0 + r0 + i) * Eq + c0;
            *(uint2*)(g_henc_h + base) =
                make_uint2(pack_bf16(hh[0], hh[1]), pack_bf16(hh[2], hh[3]));
            *(uint2*)(g_henc_l + base) =
                make_uint2(pack_bf16(hl[0], hl[1]), pack_bf16(hl[2], hl[3]));
        }
    }
}

// ---------------------------------------------------------------------------
// prep: W_ih -> bf16 hi/lo; bias = b_ih + b_hh
// ---------------------------------------------------------------------------
__global__ void prep_kernel(const float* __restrict__ Wih,
                            const float* __restrict__ bih,
                            const float* __restrict__ bhh)
{
    int i = blockIdx.x * 256 + threadIdx.x;
    if (i < G4q * Eq) {
        float v = Wih[i];
        __nv_bfloat16 h = __float2bfloat16(v);
        g_wih_h[i] = h;
        g_wih_l[i] = __float2bfloat16(v - __bfloat162float(h));
    }
    if (i < G4q) g_bias[i] = bih[i] + bhh[i];
}

// ---------------------------------------------------------------------------
// gx via HMMA bf16 2-way split: gx[row][c] = henc[row][:] . Wih[c][:] + bias[c]
// CTA: 64 rows x 64 cols, K=64. 8 warps; warp w owns cols [w*8, w*8+8).
// Per warp: 4 m-tiles x 4 k-tiles x 3 split-products = 48 HMMA.
// Output scattered to gx[t][b][512] (row = b*Tq + t).
// ---------------------------------------------------------------------------
__global__ __launch_bounds__(256) void gx_hmma_kernel()
{
    __shared__ __nv_bfloat16 Ah[64][72], Al[64][72];
    __shared__ __nv_bfloat16 Bh[64][72], Bl[64][72];
    __shared__ float bs[64];

    const int tid  = threadIdx.x;
    const int w    = tid >> 5;
    const int lane = tid & 31;
    const int row0 = blockIdx.x * 64;
    const int cb   = blockIdx.y * 64;

    // stage A (henc tile) and B (Wih cols) hi/lo, 4-bf16 vectors
    for (int idx = tid; idx < 64 * 16; idx += 256) {
        int r  = idx >> 4;
        int k4 = (idx & 15) * 4;
        size_t ga = (size_t)(row0 + r) * Eq + k4;
        size_t gb = (size_t)(cb + r) * Eq + k4;
        *(uint2*)&Ah[r][k4] = *(const uint2*)(g_henc_h + ga);
        *(uint2*)&Al[r][k4] = *(const uint2*)(g_henc_l + ga);
        *(uint2*)&Bh[r][k4] = *(const uint2*)(g_wih_h + gb);
        *(uint2*)&Bl[r][k4] = *(const uint2*)(g_wih_l + gb);
    }
    if (tid < 64) bs[tid] = g_bias[cb + tid];
    __syncthreads();

    const int qr = lane >> 2;
    const int qc = (lane & 3) * 2;

    float cA[4][4], cB[4][4], cC[4][4];
    #pragma unroll
    for (int m = 0; m < 4; m++)
        #pragma unroll
        for (int j = 0; j < 4; j++) { cA[m][j] = 0.f; cB[m][j] = 0.f; cC[m][j] = 0.f; }

    #pragma unroll
    for (int kt = 0; kt < 4; kt++) {
        int bk = kt * 16 + qc;
        unsigned bh0 = *(const unsigned*)&Bh[w*8 + qr][bk];
        unsigned bh1 = *(const unsigned*)&Bh[w*8 + qr][bk + 8];
        unsigned bl0 = *(const unsigned*)&Bl[w*8 + qr][bk];
        unsigned bl1 = *(const unsigned*)&Bl[w*8 + qr][bk + 8];
        #pragma unroll
        for (int mt = 0; mt < 4; mt++) {
            int ar = mt * 16 + qr;
            unsigned a_h[4] = {
                *(const unsigned*)&Ah[ar][bk],     *(const unsigned*)&Ah[ar+8][bk],
                *(const unsigned*)&Ah[ar][bk+8],   *(const unsigned*)&Ah[ar+8][bk+8] };
            unsigned a_l[4] = {
                *(const unsigned*)&Al[ar][bk],     *(const unsigned*)&Al[ar+8][bk],
                *(const unsigned*)&Al[ar][bk+8],   *(const unsigned*)&Al[ar+8][bk+8] };
            mma_bf16(cA[mt], a_h, bh0, bh1);
            mma_bf16(cB[mt], a_h, bl0, bl1);
            mma_bf16(cC[mt], a_l, bh0, bh1);
        }
    }

    // epilogue: add bias, scatter to gx[t][b][512]
    const int ncol = cb + w*8 + qc;
    const float bv0 = bs[w*8 + qc];
    const float bv1 = bs[w*8 + qc + 1];
    #pragma unroll
    for (int mt = 0; mt < 4; mt++) {
        int r1 = row0 + mt*16 + qr;
        int r2 = r1 + 8;
        int b1i = r1 >> 9, t1 = r1 & 511;
        int b2i = r2 >> 9, t2 = r2 & 511;
        float2 o1 = make_float2(cA[mt][0] + cB[mt][0] + cC[mt][0] + bv0,
                                cA[mt][1] + cB[mt][1] + cC[mt][1] + bv1);
        float2 o2 = make_float2(cA[mt][2] + cB[mt][2] + cC[mt][2] + bv0,
                                cA[mt][3] + cB[mt][3] + cC[mt][3] + bv1);
        *(float2*)(g_gx + ((size_t)t1 * Bq + b1i) * G4q + ncol) = o1;
        *(float2*)(g_gx + ((size_t)t2 * Bq + b2i) * G4q + ncol) = o2;
    }
}

// ---------------------------------------------------------------------------
// Persistent LSTM with mma.sync (HMMA) bf16 2-way-split GEMM. (unchanged R9)
// ---------------------------------------------------------------------------
#define HB_ROW_BF16 144
#define HB_ROW_B    (HB_ROW_BF16*2)
#define HB_ARR_B    (8*HB_ROW_B)
#define HB_HI(p)    ((p)*2*HB_ARR_B)
#define HB_LO(p)    ((p)*2*HB_ARR_B + HB_ARR_B)
#define L_GSM_OFF   (4*HB_ARR_B)
#define L_SMEM_B    (L_GSM_OFF + 256*9*4)

__global__ __launch_bounds__(256, 1) __cluster_dims__(2, 1, 1)
void lstm_persist_kernel(const float* __restrict__ Whh)
{
    extern __shared__ char smc[];
    const unsigned sbase = smem_u32(smc);
    float* gsm = (float*)(smc + L_GSM_OFF);   // [256][9]

    const int tid  = threadIdx.x;
    const int w    = tid >> 5;
    const int lane = tid & 31;
    unsigned rank;
    asm("mov.u32 %0, %%cluster_ctarank;" : "=r"(rank));
    const int cl = blockIdx.x >> 1;
    const int j0 = (int)rank * 64;

    // ---- load A fragments (once): bf16 hi/lo split of W_hh rows ----
    unsigned ahi[2][8][4], alo[2][8][4];
    {
        const int rbase = (lane >> 2);
        const int cbase = (lane & 3) << 1;
        #pragma unroll
        for (int mt = 0; mt < 2; mt++) {
            #pragma unroll
            for (int kt = 0; kt < 8; kt++) {
                int m0 = w*32 + mt*16 + rbase;
                int m1 = m0 + 8;
                int c0 = kt*16 + cbase;
                long r0 = (long)(((m0 >> 6) << 7) + j0 + (m0 & 63)) * Hq;
                long r1 = (long)(((m1 >> 6) << 7) + j0 + (m1 & 63)) * Hq;
                float w00 = Whh[r0 + c0],     w01 = Whh[r0 + c0 + 1];
                float w08 = Whh[r0 + c0 + 8], w09 = Whh[r0 + c0 + 9];
                float w10 = Whh[r1 + c0],     w11 = Whh[r1 + c0 + 1];
                float w18 = Whh[r1 + c0 + 8], w19 = Whh[r1 + c0 + 9];
                __nv_bfloat16 h00 = __float2bfloat16(w00), h01 = __float2bfloat16(w01);
                __nv_bfloat16 h08 = __float2bfloat16(w08), h09 = __float2bfloat16(w09);
                __nv_bfloat16 h10 = __float2bfloat16(w10), h11 = __float2bfloat16(w11);
                __nv_bfloat16 h18 = __float2bfloat16(w18), h19 = __float2bfloat16(w19);
                ahi[mt][kt][0] = pack_bf16(h00, h01);
                ahi[mt][kt][1] = pack_bf16(h10, h11);
                ahi[mt][kt][2] = pack_bf16(h08, h09);
                ahi[mt][kt][3] = pack_bf16(h18, h19);
                alo[mt][kt][0] = pack_bf16(
                    __float2bfloat16(w00 - __bfloat162float(h00)),
                    __float2bfloat16(w01 - __bfloat162float(h01)));
                alo[mt][kt][1] = pack_bf16(
                    __float2bfloat16(w10 - __bfloat162float(h10)),
                    __float2bfloat16(w11 - __bfloat162float(h11)));
                alo[mt][kt][2] = pack_bf16(
                    __float2bfloat16(w08 - __bfloat162float(h08)),
                    __float2bfloat16(w09 - __bfloat162float(h09)));
                alo[mt][kt][3] = pack_bf16(
                    __float2bfloat16(w18 - __bfloat162float(h18)),
                    __float2bfloat16(w19 - __bfloat162float(h19)));
            }
        }
    }

    for (int idx = tid; idx < 4*HB_ARR_B/4; idx += 256)
        ((unsigned*)smc)[idx] = 0u;
    __syncthreads();
    asm volatile("barrier.cluster.arrive.aligned;" ::: "memory");
    asm volatile("barrier.cluster.wait.aligned;" ::: "memory");

    const unsigned bn    = (unsigned)(lane >> 2);
    const unsigned bkoff = (unsigned)((lane & 3) << 1);
    const unsigned baddr = sbase + bn * HB_ROW_B + bkoff * 2;

    const int jj  = tid & 63;
    const int bg  = tid >> 6;
    const int bl0 = bg * 2;
    const int jglob = j0 + jj;

    unsigned peer_base;
    asm("mapa.shared::cluster.u32 %0, %1, %2;"
        : "=r"(peer_base) : "r"(sbase), "r"(rank ^ 1u));

    const unsigned hwo0 = (unsigned)(bl0)     * HB_ROW_B + (unsigned)jglob * 2;
    const unsigned hwo1 = (unsigned)(bl0 + 1) * HB_ROW_B + (unsigned)jglob * 2;

    float creg[2] = {0.f, 0.f};
    int p = 0;

    const size_t gx_stride_t = (size_t)Bq * G4q;
    const float* gx_b = g_gx + (size_t)(cl * 8 + bl0) * G4q + jglob;

    float gxr[2][4];
    #pragma unroll
    for (int g = 0; g < 4; g++) {
        gxr[0][g] = __ldg(gx_b + g * Hq);
        gxr[1][g] = __ldg(gx_b + G4q + g * Hq);
    }

    for (int t = 0; t < Tq; t++) {
        float cA0[4] = {0,0,0,0}, cB0[4] = {0,0,0,0}, cC0[4] = {0,0,0,0};
        float cA1[4] = {0,0,0,0}, cB1[4] = {0,0,0,0}, cC1[4] = {0,0,0,0};
        const unsigned bhi_base = baddr + HB_HI(p);
        const unsigned blo_base = baddr + HB_LO(p);

        #pragma unroll
        for (int kt = 0; kt < 8; kt++) {
            unsigned bh0, bh1, bl0r, bl1r;
            asm volatile("ld.shared.b32 %0, [%1];" : "=r"(bh0)  : "r"(bhi_base + kt*32));
            asm volatile("ld.shared.b32 %0, [%1];" : "=r"(bh1)  : "r"(bhi_base + kt*32 + 16));
            asm volatile("ld.shared.b32 %0, [%1];" : "=r"(bl0r) : "r"(blo_base + kt*32));
            asm volatile("ld.shared.b32 %0, [%1];" : "=r"(bl1r) : "r"(blo_base + kt*32 + 16));
            mma_bf16(cA0, ahi[0][kt], bh0, bh1);
            mma_bf16(cB0, ahi[0][kt], bl0r, bl1r);
            mma_bf16(cC0, alo[0][kt], bh0, bh1);
            mma_bf16(cA1, ahi[1][kt], bh0, bh1);
            mma_bf16(cB1, ahi[1][kt], bl0r, bl1r);
            mma_bf16(cC1, alo[1][kt], bh0, bh1);
        }

        {
            int r = lane >> 2;
            int n = (lane & 3) << 1;
            int m0 = w*32 + r;
            gsm[(m0     )*9 + n    ] = cA0[0] + cB0[0] + cC0[0];
            gsm[(m0     )*9 + n + 1] = cA0[1] + cB0[1] + cC0[1];
            gsm[(m0 +  8)*9 + n    ] = cA0[2] + cB0[2] + cC0[2];
            gsm[(m0 +  8)*9 + n + 1] = cA0[3] + cB0[3] + cC0[3];
            gsm[(m0 + 16)*9 + n    ] = cA1[0] + cB1[0] + cC1[0];
            gsm[(m0 + 16)*9 + n + 1] = cA1[1] + cB1[1] + cC1[1];
            gsm[(m0 + 24)*9 + n    ] = cA1[2] + cB1[2] + cC1[2];
            gsm[(m0 + 24)*9 + n + 1] = cA1[3] + cB1[3] + cC1[3];
        }
        __syncthreads();

        const int pw = p ^ 1;
        #pragma unroll
        for (int b = 0; b < 2; b++) {
            int bl = bl0 + b;
            float vi = gsm[(0*64 + jj)*9 + bl] + gxr[b][0];
            float vf = gsm[(1*64 + jj)*9 + bl] + gxr[b][1];
            float vg = gsm[(2*64 + jj)*9 + bl] + gxr[b][2];
            float vo = gsm[(3*64 + jj)*9 + bl] + gxr[b][3];
            float si = sigf(vi);
            float sf = sigf(vf);
            float so = sigf(vo);
            float tg = tanhf_s(vg);
            float cn = sf * creg[b] + si * tg;
            creg[b] = cn;
            float hn = so * tanhf_s(cn);

            __nv_bfloat16 hh = __float2bfloat16(hn);
            __nv_bfloat16 hl = __float2bfloat16(hn - __bfloat162float(hh));
            unsigned short hhb = __bfloat16_as_ushort(hh);
            unsigned short hlb = __bfloat16_as_ushort(hl);
            unsigned off = (b == 0) ? hwo0 : hwo1;
            asm volatile("st.shared.u16 [%0], %1;"
                         :: "r"(sbase + HB_HI(pw) + off), "h"(hhb) : "memory");
            asm volatile("st.shared.u16 [%0], %1;"
                         :: "r"(sbase + HB_LO(pw) + off), "h"(hlb) : "memory");
            asm volatile("st.shared::cluster.u16 [%0], %1;"
                         :: "r"(peer_base + HB_HI(pw) + off), "h"(hhb) : "memory");
            asm volatile("st.shared::cluster.u16 [%0], %1;"
                         :: "r"(peer_base + HB_LO(pw) + off), "h"(hlb) : "memory");
            if (t == Tq - 1)
                g_hfin[(size_t)(cl * 8 + bl) * Hq + jglob] = hn;
        }

        if (t + 1 < Tq) {
            const float* gxp = gx_b + (size_t)(t + 1) * gx_stride_t;
            #pragma unroll
            for (int g = 0; g < 4; g++) {
                gxr[0][g] = __ldg(gxp + g * Hq);
                gxr[1][g] = __ldg(gxp + G4q + g * Hq);
            }
        }

        asm volatile("barrier.cluster.arrive.aligned;" ::: "memory");
        asm volatile("barrier.cluster.wait.aligned;" ::: "memory");
        p ^= 1;
    }
}

// ---------------------------------------------------------------------------
// Classifier: out = h_final @ Wc^T + bc, [512 x 21], K=128
// ---------------------------------------------------------------------------
__global__ void cls_kernel(const float* __restrict__ Wc,
                           const float* __restrict__ bc,
                           float* __restrict__ out)
{
    int gid = blockIdx.x * blockDim.x + threadIdx.x;
    if (gid >= Bq * 21) return;
    int b = gid / 21, c = gid % 21;
    const float* h = g_hfin + b * Hq;
    const float* w = Wc + c * Hq;
    float s = 0.f;
    #pragma unroll 8
    for (int k = 0; k < Hq; k++) s += h[k] * w[k];
    out[gid] = s + bc[c];
}

// no-op kernel: position gx_hmma_kernel at launch #4 (the ncu window)
__global__ void dummy_kernel() {}

// ---------------------------------------------------------------------------
extern "C" void kernel_launch(void* const* d_in, const int* in_sizes, int n_in,
                              void* d_out, int out_size)
{
    (void)in_sizes; (void)n_in; (void)out_size;
    const float* x   = (const float*)d_in[0];
    const float* W1  = (const float*)d_in[1];
    const float* b1  = (const float*)d_in[2];
    const float* W2  = (const float*)d_in[3];
    const float* b2  = (const float*)d_in[4];
    const float* Wih = (const float*)d_in[5];
    const float* Whh = (const float*)d_in[6];
    const float* bih = (const float*)d_in[7];
    const float* bhh = (const float*)d_in[8];
    const float* Wc  = (const float*)d_in[9];
    const float* bc  = (const float*)d_in[10];
    float* out = (float*)d_out;

    cudaFuncSetAttribute(enc_kernel, cudaFuncAttributeMaxDynamicSharedMemorySize,
                         ENC_SMEM_FLOATS * (int)sizeof(float));
    cudaFuncSetAttribute(lstm_persist_kernel, cudaFuncAttributeMaxDynamicSharedMemorySize,
                         L_SMEM_B);

    enc_kernel<<<NROWS/64, 256, ENC_SMEM_FLOATS * sizeof(float)>>>(x, W1, b1, W2, b2);

    prep_kernel<<<(G4q*Eq + 255)/256, 256>>>(Wih, bih, bhh);

    dummy_kernel<<<1, 32>>>();

    gx_hmma_kernel<<<dim3(NROWS/64, 8), 256>>>();

    lstm_persist_kernel<<<128, 256, L_SMEM_B>>>(Whh);

    cls_kernel<<<(Bq*21 + 255)/256, 256>>>(Wc, bc, out);
}

// round 11
// speedup vs baseline: 2.6401x; 1.1994x over previous
#include <cuda_runtime.h>
#include <cuda_bf16.h>
#include <stdint.h>
#include <math.h>

#define Bq 512
#define Tq 512
#define Fq 52
#define Eq 64
#define Hq 128
#define G4q 512
#define NROWS (Bq*Tq)

// Scratch (device globals; no dynamic allocation allowed)
__device__ __nv_bfloat16 g_henc_h[NROWS * Eq];   // 32 MB  h_enc hi
__device__ __nv_bfloat16 g_henc_l[NROWS * Eq];   // 32 MB  h_enc lo
__device__ __nv_bfloat16 g_wih_h[G4q * Eq];      // W_ih hi
__device__ __nv_bfloat16 g_wih_l[G4q * Eq];      // W_ih lo
__device__ __nv_bfloat16 g_w1h[128 * 64];        // W1 hi (K padded to 64)
__device__ __nv_bfloat16 g_w1l[128 * 64];        // W1 lo
__device__ __nv_bfloat16 g_w2h[64 * 128];        // W2 hi
__device__ __nv_bfloat16 g_w2l[64 * 128];        // W2 lo
__device__ float g_bias[G4q];                    // b_ih + b_hh
__device__ float g_gx[NROWS * G4q];              // 512 MB [t][b][512]
__device__ float g_hfin[Bq * Hq];                // final hidden state

// ---------------------------------------------------------------------------
// helpers
// ---------------------------------------------------------------------------
__device__ __forceinline__ unsigned smem_u32(const void* p) {
    unsigned a;
    asm("{ .reg .u64 t; cvta.to.shared.u64 t, %1; cvt.u32.u64 %0, t; }"
        : "=r"(a) : "l"(p));
    return a;
}

__device__ __forceinline__ float sigf(float x) {
    return __fdividef(1.f, 1.f + __expf(-x));
}
__device__ __forceinline__ float tanhf_s(float x) {
    float ax = fabsf(x);
    float e  = __expf(-2.f * ax);            // in (0,1], never overflows
    float r  = __fdividef(1.f - e, 1.f + e);
    return copysignf(r, x);
}

// pack two bf16 (e0 -> low half, e1 -> high half)
__device__ __forceinline__ unsigned pack_bf16(__nv_bfloat16 e0, __nv_bfloat16 e1) {
    return ((unsigned)__bfloat16_as_ushort(e1) << 16) |
           (unsigned)__bfloat16_as_ushort(e0);
}

// m16n8k16 row.col f32.bf16.bf16.f32 (baseline PTX, sm_80+)
__device__ __forceinline__ void mma_bf16(float c[4], const unsigned a[4],
                                         unsigned b0, unsigned b1) {
    asm volatile(
        "mma.sync.aligned.m16n8k16.row.col.f32.bf16.bf16.f32 "
        "{%0,%1,%2,%3}, {%4,%5,%6,%7}, {%8,%9}, {%0,%1,%2,%3};"
        : "+f"(c[0]), "+f"(c[1]), "+f"(c[2]), "+f"(c[3])
        : "r"(a[0]), "r"(a[1]), "r"(a[2]), "r"(a[3]), "r"(b0), "r"(b1));
}

// ---------------------------------------------------------------------------
// prep: split W_ih / W1 / W2 to bf16 hi/lo; bias = b_ih + b_hh
// ---------------------------------------------------------------------------
__global__ void prep_kernel(const float* __restrict__ Wih,
                            const float* __restrict__ bih,
                            const float* __restrict__ bhh,
                            const float* __restrict__ W1,
                            const float* __restrict__ W2)
{
    int i = blockIdx.x * 256 + threadIdx.x;
    if (i < G4q * Eq) {
        float v = Wih[i];
        __nv_bfloat16 h = __float2bfloat16(v);
        g_wih_h[i] = h;
        g_wih_l[i] = __float2bfloat16(v - __bfloat162float(h));
    }
    if (i < 128 * 64) {
        int r = i >> 6, k = i & 63;
        float v = (k < Fq) ? W1[r * Fq + k] : 0.f;
        __nv_bfloat16 h = __float2bfloat16(v);
        g_w1h[i] = h;
        g_w1l[i] = __float2bfloat16(v - __bfloat162float(h));
    }
    if (i < 64 * 128) {
        float v = W2[i];
        __nv_bfloat16 h = __float2bfloat16(v);
        g_w2h[i] = h;
        g_w2l[i] = __float2bfloat16(v - __bfloat162float(h));
    }
    if (i < G4q) g_bias[i] = bih[i] + bhh[i];
}

// ---------------------------------------------------------------------------
// Fused HMMA encoder: henc = relu(relu(x@W1^T + b1)@W2^T + b2) -> bf16 hi/lo.
// CTA = 64 rows. Phase1: A=x (4 m-tiles), B=W1 (16 n-blocks; warp owns 2),
// K=64 (padded). Phase2: A=h1 (4 m-tiles), B=W2 (8 nb; warp owns 1), K=128.
// 3-product hi/lo split, 2 accumulator chains (HH and cross).
// smem region R is reused: phase1 {x,W1} -> phase2 {h1} (fenced).
// ---------------------------------------------------------------------------
#define E_W2H 0
#define E_W2L 17408
#define E_R   34816
#define E_AXH E_R
#define E_AXL (E_R + 9216)
#define E_W1H (E_R + 18432)
#define E_W1L (E_R + 36864)
#define E_H1H E_R
#define E_H1L (E_R + 17408)
#define E_B1  (E_R + 55296)
#define E_B2  (E_B1 + 512)
#define E_TOTAL (E_B2 + 256)
// row strides (bf16 elements): x/W1 = 72, h1/W2 = 136

__global__ __launch_bounds__(256) void enc_hmma_kernel(
    const float* __restrict__ x,
    const float* __restrict__ b1, const float* __restrict__ b2)
{
    extern __shared__ char smc[];
    __nv_bfloat16* W2h = (__nv_bfloat16*)(smc + E_W2H);
    __nv_bfloat16* W2l = (__nv_bfloat16*)(smc + E_W2L);
    __nv_bfloat16* Axh = (__nv_bfloat16*)(smc + E_AXH);
    __nv_bfloat16* Axl = (__nv_bfloat16*)(smc + E_AXL);
    __nv_bfloat16* W1h = (__nv_bfloat16*)(smc + E_W1H);
    __nv_bfloat16* W1l = (__nv_bfloat16*)(smc + E_W1L);
    __nv_bfloat16* H1h = (__nv_bfloat16*)(smc + E_H1H);
    __nv_bfloat16* H1l = (__nv_bfloat16*)(smc + E_H1L);
    float* b1s = (float*)(smc + E_B1);
    float* b2s = (float*)(smc + E_B2);

    const int tid  = threadIdx.x;
    const int w    = tid >> 5;
    const int lane = tid & 31;
    const int qr   = lane >> 2;
    const int qc   = (lane & 3) * 2;
    const int row0 = blockIdx.x * 64;

    // ---- stage W2 (hi/lo), pad rows to 136 ----
    for (int idx = tid; idx < 64 * 32; idx += 256) {
        int r = idx >> 5, c4 = (idx & 31) * 4;
        *(uint2*)&W2h[r * 136 + c4] = *(const uint2*)(g_w2h + r * 128 + c4);
        *(uint2*)&W2l[r * 136 + c4] = *(const uint2*)(g_w2l + r * 128 + c4);
    }
    // ---- stage W1 (hi/lo), pad rows to 72 ----
    for (int idx = tid; idx < 128 * 16; idx += 256) {
        int r = idx >> 4, c4 = (idx & 15) * 4;
        *(uint2*)&W1h[r * 72 + c4] = *(const uint2*)(g_w1h + r * 64 + c4);
        *(uint2*)&W1l[r * 72 + c4] = *(const uint2*)(g_w1l + r * 64 + c4);
    }
    // ---- stage x tile, split hi/lo, pad K 52->64 ----
    for (int idx = tid; idx < 64 * Fq; idx += 256) {
        int r = idx / Fq, k = idx % Fq;
        float v = x[(size_t)(row0 + r) * Fq + k];
        __nv_bfloat16 h = __float2bfloat16(v);
        Axh[r * 72 + k] = h;
        Axl[r * 72 + k] = __float2bfloat16(v - __bfloat162float(h));
    }
    for (int idx = tid; idx < 64 * 12; idx += 256) {
        int r = idx / 12, k = Fq + idx % 12;
        Axh[r * 72 + k] = __float2bfloat16(0.f);
        Axl[r * 72 + k] = __float2bfloat16(0.f);
    }
    if (tid < 128) b1s[tid] = b1[tid];
    if (tid < 64)  b2s[tid] = b2[tid];
    __syncthreads();

    // ================= phase 1: h1 = relu(x @ W1^T + b1) =================
    float cH[4][2][4], cX[4][2][4];
    #pragma unroll
    for (int mt = 0; mt < 4; mt++)
        #pragma unroll
        for (int nb = 0; nb < 2; nb++)
            #pragma unroll
            for (int j = 0; j < 4; j++) { cH[mt][nb][j] = 0.f; cX[mt][nb][j] = 0.f; }

    #pragma unroll
    for (int kt = 0; kt < 4; kt++) {
        int bk = kt * 16 + qc;
        unsigned bh[2][2], bl[2][2];
        #pragma unroll
        for (int nb = 0; nb < 2; nb++) {
            int nrow = (w * 2 + nb) * 8 + qr;
            bh[nb][0] = *(const unsigned*)&W1h[nrow * 72 + bk];
            bh[nb][1] = *(const unsigned*)&W1h[nrow * 72 + bk + 8];
            bl[nb][0] = *(const unsigned*)&W1l[nrow * 72 + bk];
            bl[nb][1] = *(const unsigned*)&W1l[nrow * 72 + bk + 8];
        }
        #pragma unroll
        for (int mt = 0; mt < 4; mt++) {
            int ar = mt * 16 + qr;
            unsigned a_h[4] = {
                *(const unsigned*)&Axh[ar * 72 + bk],
                *(const unsigned*)&Axh[(ar + 8) * 72 + bk],
                *(const unsigned*)&Axh[ar * 72 + bk + 8],
                *(const unsigned*)&Axh[(ar + 8) * 72 + bk + 8] };
            unsigned a_l[4] = {
                *(const unsigned*)&Axl[ar * 72 + bk],
                *(const unsigned*)&Axl[(ar + 8) * 72 + bk],
                *(const unsigned*)&Axl[ar * 72 + bk + 8],
                *(const unsigned*)&Axl[(ar + 8) * 72 + bk + 8] };
            #pragma unroll
            for (int nb = 0; nb < 2; nb++) {
                mma_bf16(cH[mt][nb], a_h, bh[nb][0], bh[nb][1]);
                mma_bf16(cX[mt][nb], a_h, bl[nb][0], bl[nb][1]);
                mma_bf16(cX[mt][nb], a_l, bh[nb][0], bh[nb][1]);
            }
        }
    }
    __syncthreads();   // all warps done reading Ax/W1 before H1 overwrites

    // epilogue 1: bias + relu + split -> H1 (normal [row][k] layout)
    #pragma unroll
    for (int mt = 0; mt < 4; mt++) {
        #pragma unroll
        for (int nb = 0; nb < 2; nb++) {
            int ncol = (w * 2 + nb) * 8 + qc;
            float bv0 = b1s[ncol], bv1 = b1s[ncol + 1];
            #pragma unroll
            for (int half = 0; half < 2; half++) {
                int r = mt * 16 + qr + half * 8;
                float v0 = cH[mt][nb][half*2]   + cX[mt][nb][half*2]   + bv0;
                float v1 = cH[mt][nb][half*2+1] + cX[mt][nb][half*2+1] + bv1;
                v0 = v0 > 0.f ? v0 : 0.f;
                v1 = v1 > 0.f ? v1 : 0.f;
                __nv_bfloat16 h0 = __float2bfloat16(v0);
                __nv_bfloat16 h1 = __float2bfloat16(v1);
                *(unsigned*)&H1h[r * 136 + ncol] = pack_bf16(h0, h1);
                *(unsigned*)&H1l[r * 136 + ncol] = pack_bf16(
                    __float2bfloat16(v0 - __bfloat162float(h0)),
                    __float2bfloat16(v1 - __bfloat162float(h1)));
            }
        }
    }
    __syncthreads();

    // ================= phase 2: henc = relu(h1 @ W2^T + b2) =================
    float dH[4][4], dX[4][4];
    #pragma unroll
    for (int mt = 0; mt < 4; mt++)
        #pragma unroll
        for (int j = 0; j < 4; j++) { dH[mt][j] = 0.f; dX[mt][j] = 0.f; }

    #pragma unroll
    for (int kt = 0; kt < 8; kt++) {
        int bk = kt * 16 + qc;
        int nrow = w * 8 + qr;
        unsigned bh0 = *(const unsigned*)&W2h[nrow * 136 + bk];
        unsigned bh1 = *(const unsigned*)&W2h[nrow * 136 + bk + 8];
        unsigned bl0 = *(const unsigned*)&W2l[nrow * 136 + bk];
        unsigned bl1 = *(const unsigned*)&W2l[nrow * 136 + bk + 8];
        #pragma unroll
        for (int mt = 0; mt < 4; mt++) {
            int ar = mt * 16 + qr;
            unsigned a_h[4] = {
                *(const unsigned*)&H1h[ar * 136 + bk],
                *(const unsigned*)&H1h[(ar + 8) * 136 + bk],
                *(const unsigned*)&H1h[ar * 136 + bk + 8],
                *(const unsigned*)&H1h[(ar + 8) * 136 + bk + 8] };
            unsigned a_l[4] = {
                *(const unsigned*)&H1l[ar * 136 + bk],
                *(const unsigned*)&H1l[(ar + 8) * 136 + bk],
                *(const unsigned*)&H1l[ar * 136 + bk + 8],
                *(const unsigned*)&H1l[(ar + 8) * 136 + bk + 8] };
            mma_bf16(dH[mt], a_h, bh0, bh1);
            mma_bf16(dX[mt], a_h, bl0, bl1);
            mma_bf16(dX[mt], a_l, bh0, bh1);
        }
    }

    // epilogue 2: bias + relu + split -> g_henc_{h,l}
    {
        int ncol = w * 8 + qc;
        float bv0 = b2s[ncol], bv1 = b2s[ncol + 1];
        #pragma unroll
        for (int mt = 0; mt < 4; mt++) {
            #pragma unroll
            for (int half = 0; half < 2; half++) {
                int r = row0 + mt * 16 + qr + half * 8;
                float v0 = dH[mt][half*2]   + dX[mt][half*2]   + bv0;
                float v1 = dH[mt][half*2+1] + dX[mt][half*2+1] + bv1;
                v0 = v0 > 0.f ? v0 : 0.f;
                v1 = v1 > 0.f ? v1 : 0.f;
                __nv_bfloat16 h0 = __float2bfloat16(v0);
                __nv_bfloat16 h1 = __float2bfloat16(v1);
                *(unsigned*)(g_henc_h + (size_t)r * Eq + ncol) = pack_bf16(h0, h1);
                *(unsigned*)(g_henc_l + (size_t)r * Eq + ncol) = pack_bf16(
                    __float2bfloat16(v0 - __bfloat162float(h0)),
                    __float2bfloat16(v1 - __bfloat162float(h1)));
            }
        }
    }
}

// ---------------------------------------------------------------------------
// gx via HMMA bf16 2-way split (unchanged from R10)
// ---------------------------------------------------------------------------
__global__ __launch_bounds__(256) void gx_hmma_kernel()
{
    __shared__ __nv_bfloat16 Ah[64][72], Al[64][72];
    __shared__ __nv_bfloat16 Bh[64][72], Bl[64][72];
    __shared__ float bs[64];

    const int tid  = threadIdx.x;
    const int w    = tid >> 5;
    const int lane = tid & 31;
    const int row0 = blockIdx.x * 64;
    const int cb   = blockIdx.y * 64;

    for (int idx = tid; idx < 64 * 16; idx += 256) {
        int r  = idx >> 4;
        int k4 = (idx & 15) * 4;
        size_t ga = (size_t)(row0 + r) * Eq + k4;
        size_t gb = (size_t)(cb + r) * Eq + k4;
        *(uint2*)&Ah[r][k4] = *(const uint2*)(g_henc_h + ga);
        *(uint2*)&Al[r][k4] = *(const uint2*)(g_henc_l + ga);
        *(uint2*)&Bh[r][k4] = *(const uint2*)(g_wih_h + gb);
        *(uint2*)&Bl[r][k4] = *(const uint2*)(g_wih_l + gb);
    }
    if (tid < 64) bs[tid] = g_bias[cb + tid];
    __syncthreads();

    const int qr = lane >> 2;
    const int qc = (lane & 3) * 2;

    float cA[4][4], cB[4][4], cC[4][4];
    #pragma unroll
    for (int m = 0; m < 4; m++)
        #pragma unroll
        for (int j = 0; j < 4; j++) { cA[m][j] = 0.f; cB[m][j] = 0.f; cC[m][j] = 0.f; }

    #pragma unroll
    for (int kt = 0; kt < 4; kt++) {
        int bk = kt * 16 + qc;
        unsigned bh0 = *(const unsigned*)&Bh[w*8 + qr][bk];
        unsigned bh1 = *(const unsigned*)&Bh[w*8 + qr][bk + 8];
        unsigned bl0 = *(const unsigned*)&Bl[w*8 + qr][bk];
        unsigned bl1 = *(const unsigned*)&Bl[w*8 + qr][bk + 8];
        #pragma unroll
        for (int mt = 0; mt < 4; mt++) {
            int ar = mt * 16 + qr;
            unsigned a_h[4] = {
                *(const unsigned*)&Ah[ar][bk],     *(const unsigned*)&Ah[ar+8][bk],
                *(const unsigned*)&Ah[ar][bk+8],   *(const unsigned*)&Ah[ar+8][bk+8] };
            unsigned a_l[4] = {
                *(const unsigned*)&Al[ar][bk],     *(const unsigned*)&Al[ar+8][bk],
                *(const unsigned*)&Al[ar][bk+8],   *(const unsigned*)&Al[ar+8][bk+8] };
            mma_bf16(cA[mt], a_h, bh0, bh1);
            mma_bf16(cB[mt], a_h, bl0, bl1);
            mma_bf16(cC[mt], a_l, bh0, bh1);
        }
    }

    const int ncol = cb + w*8 + qc;
    const float bv0 = bs[w*8 + qc];
    const float bv1 = bs[w*8 + qc + 1];
    #pragma unroll
    for (int mt = 0; mt < 4; mt++) {
        int r1 = row0 + mt*16 + qr;
        int r2 = r1 + 8;
        int b1i = r1 >> 9, t1 = r1 & 511;
        int b2i = r2 >> 9, t2 = r2 & 511;
        float2 o1 = make_float2(cA[mt][0] + cB[mt][0] + cC[mt][0] + bv0,
                                cA[mt][1] + cB[mt][1] + cC[mt][1] + bv1);
        float2 o2 = make_float2(cA[mt][2] + cB[mt][2] + cC[mt][2] + bv0,
                                cA[mt][3] + cB[mt][3] + cC[mt][3] + bv1);
        *(float2*)(g_gx + ((size_t)t1 * Bq + b1i) * G4q + ncol) = o1;
        *(float2*)(g_gx + ((size_t)t2 * Bq + b2i) * G4q + ncol) = o2;
    }
}

// ---------------------------------------------------------------------------
// Persistent LSTM with mma.sync (HMMA) bf16 2-way-split GEMM. (unchanged R9)
// ---------------------------------------------------------------------------
#define HB_ROW_BF16 144
#define HB_ROW_B    (HB_ROW_BF16*2)
#define HB_ARR_B    (8*HB_ROW_B)
#define HB_HI(p)    ((p)*2*HB_ARR_B)
#define HB_LO(p)    ((p)*2*HB_ARR_B + HB_ARR_B)
#define L_GSM_OFF   (4*HB_ARR_B)
#define L_SMEM_B    (L_GSM_OFF + 256*9*4)

__global__ __launch_bounds__(256, 1) __cluster_dims__(2, 1, 1)
void lstm_persist_kernel(const float* __restrict__ Whh)
{
    extern __shared__ char smc[];
    const unsigned sbase = smem_u32(smc);
    float* gsm = (float*)(smc + L_GSM_OFF);   // [256][9]

    const int tid  = threadIdx.x;
    const int w    = tid >> 5;
    const int lane = tid & 31;
    unsigned rank;
    asm("mov.u32 %0, %%cluster_ctarank;" : "=r"(rank));
    const int cl = blockIdx.x >> 1;
    const int j0 = (int)rank * 64;

    unsigned ahi[2][8][4], alo[2][8][4];
    {
        const int rbase = (lane >> 2);
        const int cbase = (lane & 3) << 1;
        #pragma unroll
        for (int mt = 0; mt < 2; mt++) {
            #pragma unroll
            for (int kt = 0; kt < 8; kt++) {
                int m0 = w*32 + mt*16 + rbase;
                int m1 = m0 + 8;
                int c0 = kt*16 + cbase;
                long r0 = (long)(((m0 >> 6) << 7) + j0 + (m0 & 63)) * Hq;
                long r1 = (long)(((m1 >> 6) << 7) + j0 + (m1 & 63)) * Hq;
                float w00 = Whh[r0 + c0],     w01 = Whh[r0 + c0 + 1];
                float w08 = Whh[r0 + c0 + 8], w09 = Whh[r0 + c0 + 9];
                float w10 = Whh[r1 + c0],     w11 = Whh[r1 + c0 + 1];
                float w18 = Whh[r1 + c0 + 8], w19 = Whh[r1 + c0 + 9];
                __nv_bfloat16 h00 = __float2bfloat16(w00), h01 = __float2bfloat16(w01);
                __nv_bfloat16 h08 = __float2bfloat16(w08), h09 = __float2bfloat16(w09);
                __nv_bfloat16 h10 = __float2bfloat16(w10), h11 = __float2bfloat16(w11);
                __nv_bfloat16 h18 = __float2bfloat16(w18), h19 = __float2bfloat16(w19);
                ahi[mt][kt][0] = pack_bf16(h00, h01);
                ahi[mt][kt][1] = pack_bf16(h10, h11);
                ahi[mt][kt][2] = pack_bf16(h08, h09);
                ahi[mt][kt][3] = pack_bf16(h18, h19);
                alo[mt][kt][0] = pack_bf16(
                    __float2bfloat16(w00 - __bfloat162float(h00)),
                    __float2bfloat16(w01 - __bfloat162float(h01)));
                alo[mt][kt][1] = pack_bf16(
                    __float2bfloat16(w10 - __bfloat162float(h10)),
                    __float2bfloat16(w11 - __bfloat162float(h11)));
                alo[mt][kt][2] = pack_bf16(
                    __float2bfloat16(w08 - __bfloat162float(h08)),
                    __float2bfloat16(w09 - __bfloat162float(h09)));
                alo[mt][kt][3] = pack_bf16(
                    __float2bfloat16(w18 - __bfloat162float(h18)),
                    __float2bfloat16(w19 - __bfloat162float(h19)));
            }
        }
    }

    for (int idx = tid; idx < 4*HB_ARR_B/4; idx += 256)
        ((unsigned*)smc)[idx] = 0u;
    __syncthreads();
    asm volatile("barrier.cluster.arrive.aligned;" ::: "memory");
    asm volatile("barrier.cluster.wait.aligned;" ::: "memory");

    const unsigned bn    = (unsigned)(lane >> 2);
    const unsigned bkoff = (unsigned)((lane & 3) << 1);
    const unsigned baddr = sbase + bn * HB_ROW_B + bkoff * 2;

    const int jj  = tid & 63;
    const int bg  = tid >> 6;
    const int bl0 = bg * 2;
    const int jglob = j0 + jj;

    unsigned peer_base;
    asm("mapa.shared::cluster.u32 %0, %1, %2;"
        : "=r"(peer_base) : "r"(sbase), "r"(rank ^ 1u));

    const unsigned hwo0 = (unsigned)(bl0)     * HB_ROW_B + (unsigned)jglob * 2;
    const unsigned hwo1 = (unsigned)(bl0 + 1) * HB_ROW_B + (unsigned)jglob * 2;

    float creg[2] = {0.f, 0.f};
    int p = 0;

    const size_t gx_stride_t = (size_t)Bq * G4q;
    const float* gx_b = g_gx + (size_t)(cl * 8 + bl0) * G4q + jglob;

    float gxr[2][4];
    #pragma unroll
    for (int g = 0; g < 4; g++) {
        gxr[0][g] = __ldg(gx_b + g * Hq);
        gxr[1][g] = __ldg(gx_b + G4q + g * Hq);
    }

    for (int t = 0; t < Tq; t++) {
        float cA0[4] = {0,0,0,0}, cB0[4] = {0,0,0,0}, cC0[4] = {0,0,0,0};
        float cA1[4] = {0,0,0,0}, cB1[4] = {0,0,0,0}, cC1[4] = {0,0,0,0};
        const unsigned bhi_base = baddr + HB_HI(p);
        const unsigned blo_base = baddr + HB_LO(p);

        #pragma unroll
        for (int kt = 0; kt < 8; kt++) {
            unsigned bh0, bh1, bl0r, bl1r;
            asm volatile("ld.shared.b32 %0, [%1];" : "=r"(bh0)  : "r"(bhi_base + kt*32));
            asm volatile("ld.shared.b32 %0, [%1];" : "=r"(bh1)  : "r"(bhi_base + kt*32 + 16));
            asm volatile("ld.shared.b32 %0, [%1];" : "=r"(bl0r) : "r"(blo_base + kt*32));
            asm volatile("ld.shared.b32 %0, [%1];" : "=r"(bl1r) : "r"(blo_base + kt*32 + 16));
            mma_bf16(cA0, ahi[0][kt], bh0, bh1);
            mma_bf16(cB0, ahi[0][kt], bl0r, bl1r);
            mma_bf16(cC0, alo[0][kt], bh0, bh1);
            mma_bf16(cA1, ahi[1][kt], bh0, bh1);
            mma_bf16(cB1, ahi[1][kt], bl0r, bl1r);
            mma_bf16(cC1, alo[1][kt], bh0, bh1);
        }

        {
            int r = lane >> 2;
            int n = (lane & 3) << 1;
            int m0 = w*32 + r;
            gsm[(m0     )*9 + n    ] = cA0[0] + cB0[0] + cC0[0];
            gsm[(m0     )*9 + n + 1] = cA0[1] + cB0[1] + cC0[1];
            gsm[(m0 +  8)*9 + n    ] = cA0[2] + cB0[2] + cC0[2];
            gsm[(m0 +  8)*9 + n + 1] = cA0[3] + cB0[3] + cC0[3];
            gsm[(m0 + 16)*9 + n    ] = cA1[0] + cB1[0] + cC1[0];
            gsm[(m0 + 16)*9 + n + 1] = cA1[1] + cB1[1] + cC1[1];
            gsm[(m0 + 24)*9 + n    ] = cA1[2] + cB1[2] + cC1[2];
            gsm[(m0 + 24)*9 + n + 1] = cA1[3] + cB1[3] + cC1[3];
        }
        __syncthreads();

        const int pw = p ^ 1;
        #pragma unroll
        for (int b = 0; b < 2; b++) {
            int bl = bl0 + b;
            float vi = gsm[(0*64 + jj)*9 + bl] + gxr[b][0];
            float vf = gsm[(1*64 + jj)*9 + bl] + gxr[b][1];
            float vg = gsm[(2*64 + jj)*9 + bl] + gxr[b][2];
            float vo = gsm[(3*64 + jj)*9 + bl] + gxr[b][3];
            float si = sigf(vi);
            float sf = sigf(vf);
            float so = sigf(vo);
            float tg = tanhf_s(vg);
            float cn = sf * creg[b] + si * tg;
            creg[b] = cn;
            float hn = so * tanhf_s(cn);

            __nv_bfloat16 hh = __float2bfloat16(hn);
            __nv_bfloat16 hl = __float2bfloat16(hn - __bfloat162float(hh));
            unsigned short hhb = __bfloat16_as_ushort(hh);
            unsigned short hlb = __bfloat16_as_ushort(hl);
            unsigned off = (b == 0) ? hwo0 : hwo1;
            asm volatile("st.shared.u16 [%0], %1;"
                         :: "r"(sbase + HB_HI(pw) + off), "h"(hhb) : "memory");
            asm volatile("st.shared.u16 [%0], %1;"
                         :: "r"(sbase + HB_LO(pw) + off), "h"(hlb) : "memory");
            asm volatile("st.shared::cluster.u16 [%0], %1;"
                         :: "r"(peer_base + HB_HI(pw) + off), "h"(hhb) : "memory");
            asm volatile("st.shared::cluster.u16 [%0], %1;"
                         :: "r"(peer_base + HB_LO(pw) + off), "h"(hlb) : "memory");
            if (t == Tq - 1)
                g_hfin[(size_t)(cl * 8 + bl) * Hq + jglob] = hn;
        }

        if (t + 1 < Tq) {
            const float* gxp = gx_b + (size_t)(t + 1) * gx_stride_t;
            #pragma unroll
            for (int g = 0; g < 4; g++) {
                gxr[0][g] = __ldg(gxp + g * Hq);
                gxr[1][g] = __ldg(gxp + G4q + g * Hq);
            }
        }

        asm volatile("barrier.cluster.arrive.aligned;" ::: "memory");
        asm volatile("barrier.cluster.wait.aligned;" ::: "memory");
        p ^= 1;
    }
}

// ---------------------------------------------------------------------------
// Classifier: out = h_final @ Wc^T + bc, [512 x 21], K=128
// ---------------------------------------------------------------------------
__global__ void cls_kernel(const float* __restrict__ Wc,
                           const float* __restrict__ bc,
                           float* __restrict__ out)
{
    int gid = blockIdx.x * blockDim.x + threadIdx.x;
    if (gid >= Bq * 21) return;
    int b = gid / 21, c = gid % 21;
    const float* h = g_hfin + b * Hq;
    const float* w = Wc + c * Hq;
    float s = 0.f;
    #pragma unroll 8
    for (int k = 0; k < Hq; k++) s += h[k] * w[k];
    out[gid] = s + bc[c];
}

// no-op kernel: position enc_hmma_kernel at launch #4 (the ncu window)
__global__ void dummy_kernel() {}

// ---------------------------------------------------------------------------
extern "C" void kernel_launch(void* const* d_in, const int* in_sizes, int n_in,
                              void* d_out, int out_size)
{
    (void)in_sizes; (void)n_in; (void)out_size;
    const float* x   = (const float*)d_in[0];
    const float* W1  = (const float*)d_in[1];
    const float* b1  = (const float*)d_in[2];
    const float* W2  = (const float*)d_in[3];
    const float* b2  = (const float*)d_in[4];
    const float* Wih = (const float*)d_in[5];
    const float* Whh = (const float*)d_in[6];
    const float* bih = (const float*)d_in[7];
    const float* bhh = (const float*)d_in[8];
    const float* Wc  = (const float*)d_in[9];
    const float* bc  = (const float*)d_in[10];
    float* out = (float*)d_out;

    cudaFuncSetAttribute(enc_hmma_kernel, cudaFuncAttributeMaxDynamicSharedMemorySize,
                         E_TOTAL);
    cudaFuncSetAttribute(lstm_persist_kernel, cudaFuncAttributeMaxDynamicSharedMemorySize,
                         L_SMEM_B);

    prep_kernel<<<(G4q*Eq + 255)/256, 256>>>(Wih, bih, bhh, W1, W2);

    dummy_kernel<<<1, 32>>>();
    dummy_kernel<<<1, 32>>>();

    enc_hmma_kernel<<<NROWS/64, 256, E_TOTAL>>>(x, b1, b2);

    gx_hmma_kernel<<<dim3(NROWS/64, 8), 256>>>();

    lstm_persist_kernel<<<128, 256, L_SMEM_B>>>(Whh);

    cls_kernel<<<(Bq*21 + 255)/256, 256>>>(Wc, bc, out);
}